// round 10
// baseline (speedup 1.0000x reference)
#include <cuda_runtime.h>
#include <math.h>
#include <stdint.h>

#define Bsz   4
#define Nseq  2048
#define Dm    512
#define Hh    8
#define HDim  64
#define MLPH  2048
#define ROWS  (Bsz * Nseq)
#define SCALE 0.125f

// ---------------- scratch ----------------
__device__ float g_h[ROWS * Dm];
__device__ float g_qkv[ROWS * 3 * Dm];
__device__ float g_attn[ROWS * Dm];
__device__ float g_x1[ROWS * Dm];
__device__ float g_act[ROWS * MLPH];
__device__ float g_wt[3145728];
__device__ float g_vT[Bsz * Hh * HDim * Nseq];
#define WT_QKV  0
#define WT_PROJ 786432
#define WT_FC1  1048576
#define WT_FC2  2097152

// ---------------- helpers ----------------
__device__ __forceinline__ uint32_t cvt_tf32(float x) {
    uint32_t r; asm("cvt.rna.tf32.f32 %0, %1;" : "=r"(r) : "f"(x)); return r;
}
__device__ __forceinline__ float round_tf32(float x) {
    return __uint_as_float(cvt_tf32(x));
}
__device__ __forceinline__ uint32_t smem_u32(const void* p) {
    return (uint32_t)__cvta_generic_to_shared(p);
}
__device__ __forceinline__ void ldsm4(uint32_t r[4], uint32_t a) {
    asm volatile("ldmatrix.sync.aligned.m8n8.x4.shared.b16 {%0,%1,%2,%3}, [%4];"
        : "=r"(r[0]), "=r"(r[1]), "=r"(r[2]), "=r"(r[3]) : "r"(a));
}
__device__ __forceinline__ void mma8(float d[4], const uint32_t a[4],
                                     uint32_t b0, uint32_t b1) {
    asm volatile(
        "mma.sync.aligned.m16n8k8.row.col.f32.tf32.tf32.f32 "
        "{%0,%1,%2,%3}, {%4,%5,%6,%7}, {%8,%9}, {%0,%1,%2,%3};"
        : "+f"(d[0]), "+f"(d[1]), "+f"(d[2]), "+f"(d[3])
        : "r"(a[0]), "r"(a[1]), "r"(a[2]), "r"(a[3]), "r"(b0), "r"(b1));
}
__device__ __forceinline__ void cpa16(uint32_t dst, const void* src) {
    asm volatile("cp.async.cg.shared.global [%0], [%1], 16;\n"
        :: "r"(dst), "l"(src));
}
#define CP_COMMIT() asm volatile("cp.async.commit_group;\n" ::: "memory")
#define CP_WAIT1()  asm volatile("cp.async.wait_group 1;\n" ::: "memory")
#define CP_WAIT0()  asm volatile("cp.async.wait_group 0;\n" ::: "memory")

// ---------------- merged weight transpose + tf32 round (1 launch) --------
__global__ __launch_bounds__(256) void transpose_all(
    const float* __restrict__ qkvw, const float* __restrict__ projw,
    const float* __restrict__ fc1w, const float* __restrict__ fc2w,
    float* __restrict__ wt)
{
    __shared__ float t[32][33];
    int bid = blockIdx.x;
    const float* in; float* out; int K, N, rel, nx;
    if (bid < 768)       { in = qkvw;  out = wt + WT_QKV;  K = 512;  N = 1536; rel = bid;        nx = 48; }
    else if (bid < 1024) { in = projw; out = wt + WT_PROJ; K = 512;  N = 512;  rel = bid - 768;  nx = 16; }
    else if (bid < 2048) { in = fc1w;  out = wt + WT_FC1;  K = 512;  N = 2048; rel = bid - 1024; nx = 64; }
    else                 { in = fc2w;  out = wt + WT_FC2;  K = 2048; N = 512;  rel = bid - 2048; nx = 16; }
    int n0 = (rel % nx) * 32, k0 = (rel / nx) * 32;
    int tx = threadIdx.x, ty = threadIdx.y;
    #pragma unroll
    for (int j = 0; j < 32; j += 8)
        t[ty + j][tx] = in[(size_t)(k0 + ty + j) * N + n0 + tx];
    __syncthreads();
    #pragma unroll
    for (int j = 0; j < 32; j += 8)
        out[(size_t)(n0 + ty + j) * K + k0 + tx] = round_tf32(t[tx][ty + j]);
}

// ---------------- V transpose ----------------
__global__ __launch_bounds__(256) void vtrans_kernel(
    const float* __restrict__ qkv, float* __restrict__ vT)
{
    __shared__ float t[32][33];
    int bh = blockIdx.z;
    int b = bh >> 3, h = bh & 7;
    int n0 = blockIdx.x * 32, e0 = blockIdx.y * 32;
    int tx = threadIdx.x, ty = threadIdx.y;
    const float* src = qkv + (size_t)(b * Nseq) * (3 * Dm) + 2 * Dm + h * HDim;
    #pragma unroll
    for (int j = 0; j < 32; j += 8)
        t[ty + j][tx] = src[(size_t)(n0 + ty + j) * (3 * Dm) + e0 + tx];
    __syncthreads();
    #pragma unroll
    for (int j = 0; j < 32; j += 8)
        vT[(size_t)(bh * HDim + e0 + ty + j) * Nseq + n0 + tx] = t[tx][ty + j];
}

// ---------------- LayerNorm ----------------
__global__ __launch_bounds__(128) void ln_kernel(
    const float* __restrict__ in, const float* __restrict__ gamma,
    const float* __restrict__ beta, float* __restrict__ out)
{
    int row = blockIdx.x;
    int tid = threadIdx.x;
    const float4* p = (const float4*)(in + (size_t)row * Dm);
    float4 v = p[tid];
    float s  = v.x + v.y + v.z + v.w;
    float ss = v.x * v.x + v.y * v.y + v.z * v.z + v.w * v.w;
    #pragma unroll
    for (int o = 16; o; o >>= 1) {
        s  += __shfl_xor_sync(0xffffffffu, s,  o);
        ss += __shfl_xor_sync(0xffffffffu, ss, o);
    }
    __shared__ float sm[8];
    int w = tid >> 5, lane = tid & 31;
    if (lane == 0) { sm[w] = s; sm[4 + w] = ss; }
    __syncthreads();
    float tot  = sm[0] + sm[1] + sm[2] + sm[3];
    float tot2 = sm[4] + sm[5] + sm[6] + sm[7];
    float mean = tot * (1.0f / Dm);
    float var  = tot2 * (1.0f / Dm) - mean * mean;
    float inv  = rsqrtf(var + 1e-5f);
    float4 g4 = ((const float4*)gamma)[tid];
    float4 b4 = ((const float4*)beta)[tid];
    float4 o;
    o.x = round_tf32((v.x - mean) * inv * g4.x + b4.x);
    o.y = round_tf32((v.y - mean) * inv * g4.y + b4.y);
    o.z = round_tf32((v.z - mean) * inv * g4.z + b4.z);
    o.w = round_tf32((v.w - mean) * inv * g4.w + b4.w);
    ((float4*)(out + (size_t)row * Dm))[tid] = o;
}

// ---------------- TF32 GEMM v4: 64x64 warp tiles, BK=16, 3 blocks/SM -----
// block 128x128, 4 warps (2x2), 3-stage cp.async, R3-verified swizzle:
//   phys(row, c16B) = row*64B + ((c ^ ((row>>1)&3))*16B)
#define GSTG_B  8192                  // bytes per A (or B) stage
#define GBOFF   24576                 // B region byte offset (3 A stages)
#define GSMEM_B 49152

__device__ __forceinline__ float gelu_exact(float x) {
    return 0.5f * x * (1.0f + erff(x * 0.70710678118654752f));
}

template<int N, int K, bool BIAS, bool GELU, bool RES, bool ROUND>
__global__ __launch_bounds__(128, 3) void tgemm(
    const float* __restrict__ A, const float* __restrict__ WT,
    const float* __restrict__ bias, const float* __restrict__ res,
    float* __restrict__ C)
{
    extern __shared__ uint32_t gsm[];
    uint32_t smb = smem_u32(gsm);

    int tid = threadIdx.x, lane = tid & 31, warp = tid >> 5;
    int brow = blockIdx.y * 128, bcol = blockIdx.x * 128;
    int wm = (warp >> 1) * 64, wn = (warp & 1) * 64;
    int la = lane & 7, grp = lane >> 3, g = lane >> 2, t = lane & 3;

    // staging: chunk ci = tid + 128*i (i=0..3): row = ci>>2, c = ci&3
    uint32_t dAc[4], dBc[4];
    const float *Agc[4], *Bgc[4];
    #pragma unroll
    for (int i = 0; i < 4; i++) {
        int ci = tid + 128 * i;
        int row = ci >> 2, c = ci & 3;
        Agc[i] = A  + (size_t)(brow + row) * K + c * 4;
        Bgc[i] = WT + (size_t)(bcol + row) * K + c * 4;
        uint32_t off = (uint32_t)(row * 64 + ((c ^ ((row >> 1) & 3)) << 4));
        dAc[i] = smb + off;
        dBc[i] = smb + GBOFF + off;
    }

    // ldsm addresses: 4 A m-tiles, 4 B n-tiles
    uint32_t aAddr[4];
    #pragma unroll
    for (int mi = 0; mi < 4; mi++) {
        int r = wm + mi * 16 + la + (grp & 1) * 8;
        int c = grp >> 1;
        aAddr[mi] = smb + (uint32_t)(r * 64 + ((c ^ ((r >> 1) & 3)) << 4));
    }
    uint32_t bAddr[4];
    #pragma unroll
    for (int nt = 0; nt < 4; nt++) {
        int n = wn + nt * 16 + (lane & 7) + ((lane >> 4) & 1) * 8;
        int c = (lane >> 3) & 1;
        bAddr[nt] = smb + GBOFF + (uint32_t)(n * 64 + ((c ^ ((n >> 1) & 3)) << 4));
    }

    float acc[4][8][4];
    #pragma unroll
    for (int mi = 0; mi < 4; mi++)
        #pragma unroll
        for (int ni = 0; ni < 8; ni++)
            #pragma unroll
            for (int c = 0; c < 4; c++) acc[mi][ni][c] = 0.0f;

    constexpr int iters = K / 16;

    // prologue: prefetch stages 0,1
    #pragma unroll
    for (int p = 0; p < 2; p++) {
        #pragma unroll
        for (int i = 0; i < 4; i++) {
            cpa16(dAc[i] + p * GSTG_B, Agc[i] + p * 16);
            cpa16(dBc[i] + p * GSTG_B, Bgc[i] + p * 16);
        }
        CP_COMMIT();
    }

    #pragma unroll 1
    for (int it = 0; it < iters; ++it) {
        CP_WAIT1();
        __syncthreads();
        if (it + 2 < iters) {
            uint32_t so = (uint32_t)(((it + 2) % 3) * GSTG_B);
            #pragma unroll
            for (int i = 0; i < 4; i++) {
                cpa16(dAc[i] + so, Agc[i] + (it + 2) * 16);
                cpa16(dBc[i] + so, Bgc[i] + (it + 2) * 16);
            }
        }
        CP_COMMIT();

        uint32_t so = (uint32_t)((it % 3) * GSTG_B);
        #pragma unroll
        for (int ks = 0; ks < 2; ks++) {
            uint32_t kx = (uint32_t)(ks << 5);
            uint32_t af[4][4];
            #pragma unroll
            for (int mi = 0; mi < 4; mi++)
                ldsm4(af[mi], (aAddr[mi] + so) ^ kx);
            #pragma unroll
            for (int nt = 0; nt < 4; nt++) {
                uint32_t bf[4];
                ldsm4(bf, (bAddr[nt] + so) ^ kx);
                #pragma unroll
                for (int mi = 0; mi < 4; mi++) {
                    mma8(acc[mi][nt * 2],     af[mi], bf[0], bf[1]);
                    mma8(acc[mi][nt * 2 + 1], af[mi], bf[2], bf[3]);
                }
            }
        }
    }

    // epilogue
    #pragma unroll
    for (int mi = 0; mi < 4; mi++) {
        int r0e = brow + wm + mi * 16 + g;
        #pragma unroll
        for (int ni = 0; ni < 8; ni++) {
            int col = bcol + wn + ni * 8 + t * 2;
            float2 v0 = {acc[mi][ni][0], acc[mi][ni][1]};
            float2 v1 = {acc[mi][ni][2], acc[mi][ni][3]};
            if (BIAS) {
                float2 bb = *(const float2*)&bias[col];
                v0.x += bb.x; v0.y += bb.y; v1.x += bb.x; v1.y += bb.y;
            }
            if (GELU) {
                v0.x = gelu_exact(v0.x); v0.y = gelu_exact(v0.y);
                v1.x = gelu_exact(v1.x); v1.y = gelu_exact(v1.y);
            }
            if (RES) {
                float2 q0 = *(const float2*)&res[(size_t)r0e * N + col];
                float2 q1 = *(const float2*)&res[(size_t)(r0e + 8) * N + col];
                v0.x += q0.x; v0.y += q0.y; v1.x += q1.x; v1.y += q1.y;
            }
            if (ROUND) {
                v0.x = round_tf32(v0.x); v0.y = round_tf32(v0.y);
                v1.x = round_tf32(v1.x); v1.y = round_tf32(v1.y);
            }
            *(float2*)&C[(size_t)r0e * N + col] = v0;
            *(float2*)&C[(size_t)(r0e + 8) * N + col] = v1;
        }
    }
}

// ---------------- TF32 flash attention (unchanged) ----------------
#define KPW      68
#define OFF_QP   0
#define OFF_K    8704
#define OFF_V    17408
#define OFF_EK   26112
#define ATT_WORDS 26240
#define ATT_BYTES (ATT_WORDS * 4)
#define KVSTG    4352

__device__ __forceinline__ float bias_f(float eq, float ek, float alpha) {
    float diff = (ek - eq) * 1e-3f;
    float b = -alpha * fmaxf(diff, 0.0f);
    return fminf(fmaxf(b, -10.0f), 0.0f);
}

__global__ __launch_bounds__(256, 2) void attn_tc(
    const float* __restrict__ qkv, const float* __restrict__ vT,
    const float* __restrict__ elev, const float* __restrict__ alpha_p,
    float* __restrict__ out)
{
    extern __shared__ uint32_t dsm[];
    uint32_t smb = smem_u32(dsm);
    float* sEK = (float*)(dsm + OFF_EK);

    int bh = blockIdx.y;
    int b = bh >> 3, h = bh & 7;
    int q0 = blockIdx.x * 128;
    int tid = threadIdx.x, lane = tid & 31, warp = tid >> 5;
    int la = lane & 7, grp = lane >> 3, g = lane >> 2, t = lane & 3;
    float alpha = alpha_p[0];
    const float* eb = elev + b * Nseq;
    const float* qbase = qkv + ((size_t)(b * Nseq + q0)) * (3 * Dm) + h * HDim;
    const float* kvb   = qkv + ((size_t)(b * Nseq)) * (3 * Dm) + Dm + h * HDim;
    const float* vtb   = vT + (size_t)(bh * HDim) * Nseq;

    #pragma unroll
    for (int i = 0; i < 8; i++) {
        int idx = tid + i * 256;
        int r = idx >> 4, c4 = (idx & 15) * 4;
        cpa16(smb + (uint32_t)(OFF_QP + r * KPW + c4) * 4u,
              qbase + (size_t)r * (3 * Dm) + c4);
    }
    #pragma unroll
    for (int i = 0; i < 4; i++) {
        int idx = tid + i * 256;
        int r = idx >> 4, c4 = (idx & 15) * 4;
        cpa16(smb + (uint32_t)(OFF_K + r * KPW + c4) * 4u,
              kvb + (size_t)r * (3 * Dm) + c4);
        cpa16(smb + (uint32_t)(OFF_V + r * KPW + c4) * 4u,
              vtb + (size_t)r * Nseq + c4);
    }
    if (tid < 64) sEK[tid] = eb[tid];
    CP_COMMIT();
    CP_WAIT0();
    __syncthreads();

    int qr0 = warp * 16;
    uint32_t aAddr = smb +
        (uint32_t)(OFF_QP + (qr0 + la + (grp & 1) * 8) * KPW + (grp >> 1) * 4) * 4u;
    uint32_t qf[8][4];
    #pragma unroll
    for (int kc = 0; kc < 8; kc++) ldsm4(qf[kc], aAddr + kc * 32);

    float eq0 = eb[q0 + qr0 + g];
    float eq1 = eb[q0 + qr0 + g + 8];

    uint32_t bAddrK[4], bAddrV[4];
    #pragma unroll
    for (int nt = 0; nt < 4; nt++) {
        int r = nt * 16 + la + (grp >> 1) * 8;
        bAddrK[nt] = smb + (uint32_t)(OFF_K + r * KPW + (grp & 1) * 4) * 4u;
        bAddrV[nt] = smb + (uint32_t)(OFF_V + r * KPW + (grp & 1) * 4) * 4u;
    }

    float O[8][4];
    #pragma unroll
    for (int e = 0; e < 8; e++)
        O[e][0] = O[e][1] = O[e][2] = O[e][3] = 0.0f;
    float mi0 = -1e30f, mi1 = -1e30f, li0 = 0.0f, li1 = 0.0f;

    #pragma unroll 1
    for (int tt = 0; tt < Nseq / 64; tt++) {
        if (tt) { CP_WAIT0(); __syncthreads(); }
        if (tt + 1 < Nseq / 64) {
            int bufn = (tt + 1) & 1;
            int k0n = (tt + 1) * 64;
            const float* kb = kvb + (size_t)k0n * (3 * Dm);
            #pragma unroll
            for (int i = 0; i < 4; i++) {
                int idx = tid + i * 256;
                int r = idx >> 4, c4 = (idx & 15) * 4;
                cpa16(smb + (uint32_t)(OFF_K + bufn * KVSTG + r * KPW + c4) * 4u,
                      kb + (size_t)r * (3 * Dm) + c4);
                cpa16(smb + (uint32_t)(OFF_V + bufn * KVSTG + r * KPW + c4) * 4u,
                      vtb + (size_t)r * Nseq + k0n + c4);
            }
            if (tid < 64) sEK[bufn * 64 + tid] = eb[k0n + tid];
        }
        CP_COMMIT();

        int buf = tt & 1;
        uint32_t bOff = (uint32_t)(buf * KVSTG) * 4u;

        float S[8][4];
        #pragma unroll
        for (int nt = 0; nt < 8; nt++)
            S[nt][0] = S[nt][1] = S[nt][2] = S[nt][3] = 0.0f;
        #pragma unroll
        for (int kc = 0; kc < 8; kc++) {
            #pragma unroll
            for (int nt4 = 0; nt4 < 4; nt4++) {
                uint32_t bf[4];
                ldsm4(bf, bAddrK[nt4] + bOff + kc * 32);
                mma8(S[nt4 * 2], qf[kc], bf[0], bf[1]);
                mma8(S[nt4 * 2 + 1], qf[kc], bf[2], bf[3]);
            }
        }

        float rm0 = -1e30f, rm1 = -1e30f;
        #pragma unroll
        for (int nt = 0; nt < 8; nt++) {
            float ek0 = sEK[buf * 64 + nt * 8 + t * 2];
            float ek1 = sEK[buf * 64 + nt * 8 + t * 2 + 1];
            S[nt][0] = S[nt][0] * SCALE + bias_f(eq0, ek0, alpha);
            S[nt][1] = S[nt][1] * SCALE + bias_f(eq0, ek1, alpha);
            S[nt][2] = S[nt][2] * SCALE + bias_f(eq1, ek0, alpha);
            S[nt][3] = S[nt][3] * SCALE + bias_f(eq1, ek1, alpha);
            rm0 = fmaxf(rm0, fmaxf(S[nt][0], S[nt][1]));
            rm1 = fmaxf(rm1, fmaxf(S[nt][2], S[nt][3]));
        }
        rm0 = fmaxf(rm0, __shfl_xor_sync(0xffffffffu, rm0, 1));
        rm0 = fmaxf(rm0, __shfl_xor_sync(0xffffffffu, rm0, 2));
        rm1 = fmaxf(rm1, __shfl_xor_sync(0xffffffffu, rm1, 1));
        rm1 = fmaxf(rm1, __shfl_xor_sync(0xffffffffu, rm1, 2));
        float mn0 = fmaxf(mi0, rm0), mn1 = fmaxf(mi1, rm1);
        float c0 = __expf(mi0 - mn0), c1 = __expf(mi1 - mn1);
        mi0 = mn0; mi1 = mn1;
        float rs0 = 0.0f, rs1 = 0.0f;
        #pragma unroll
        for (int nt = 0; nt < 8; nt++) {
            S[nt][0] = __expf(S[nt][0] - mn0); rs0 += S[nt][0];
            S[nt][1] = __expf(S[nt][1] - mn0); rs0 += S[nt][1];
            S[nt][2] = __expf(S[nt][2] - mn1); rs1 += S[nt][2];
            S[nt][3] = __expf(S[nt][3] - mn1); rs1 += S[nt][3];
        }
        rs0 += __shfl_xor_sync(0xffffffffu, rs0, 1);
        rs0 += __shfl_xor_sync(0xffffffffu, rs0, 2);
        rs1 += __shfl_xor_sync(0xffffffffu, rs1, 1);
        rs1 += __shfl_xor_sync(0xffffffffu, rs1, 2);
        li0 = li0 * c0 + rs0;
        li1 = li1 * c1 + rs1;
        #pragma unroll
        for (int e = 0; e < 8; e++) {
            O[e][0] *= c0; O[e][1] *= c0; O[e][2] *= c1; O[e][3] *= c1;
        }

        #pragma unroll
        for (int nt = 0; nt < 8; nt++) {
            uint32_t* p0 = &dsm[OFF_QP + (qr0 + g) * KPW + nt * 8 + t * 2];
            uint32_t* p1 = &dsm[OFF_QP + (qr0 + 8 + g) * KPW + nt * 8 + t * 2];
            p0[0] = cvt_tf32(S[nt][0]); p0[1] = cvt_tf32(S[nt][1]);
            p1[0] = cvt_tf32(S[nt][2]); p1[1] = cvt_tf32(S[nt][3]);
        }
        __syncwarp();

        #pragma unroll
        for (int kc = 0; kc < 8; kc++) {
            uint32_t pf[4];
            ldsm4(pf, aAddr + kc * 32);
            #pragma unroll
            for (int nt4 = 0; nt4 < 4; nt4++) {
                uint32_t bf[4];
                ldsm4(bf, bAddrV[nt4] + bOff + kc * 32);
                mma8(O[nt4 * 2],     pf, bf[0], bf[1]);
                mma8(O[nt4 * 2 + 1], pf, bf[2], bf[3]);
            }
        }
    }

    float inv0 = 1.0f / li0, inv1 = 1.0f / li1;
    int row0 = b * Nseq + q0 + qr0 + g;
    #pragma unroll
    for (int e = 0; e < 8; e++) {
        int col = h * HDim + e * 8 + t * 2;
        float2 o0 = {round_tf32(O[e][0] * inv0), round_tf32(O[e][1] * inv0)};
        float2 o1 = {round_tf32(O[e][2] * inv1), round_tf32(O[e][3] * inv1)};
        *(float2*)&out[(size_t)row0 * Dm + col] = o0;
        *(float2*)&out[(size_t)(row0 + 8) * Dm + col] = o1;
    }
}

// ---------------- launch ----------------
extern "C" void kernel_launch(void* const* d_in, const int* in_sizes, int n_in,
                              void* d_out, int out_size)
{
    const float* x     = (const float*)d_in[0];
    const float* elev  = (const float*)d_in[1];
    const float* ln1g  = (const float*)d_in[2];
    const float* ln1b  = (const float*)d_in[3];
    const float* qkvw  = (const float*)d_in[4];
    const float* alpha = (const float*)d_in[5];
    const float* projw = (const float*)d_in[6];
    const float* projb = (const float*)d_in[7];
    const float* ln2g  = (const float*)d_in[8];
    const float* ln2b  = (const float*)d_in[9];
    const float* fc1w  = (const float*)d_in[10];
    const float* fc1b  = (const float*)d_in[11];
    const float* fc2w  = (const float*)d_in[12];
    const float* fc2b  = (const float*)d_in[13];
    float* out = (float*)d_out;

    float *ph, *pqkv, *pattn, *px1, *pact, *pwt, *pvt;
    cudaGetSymbolAddress((void**)&ph,    g_h);
    cudaGetSymbolAddress((void**)&pqkv,  g_qkv);
    cudaGetSymbolAddress((void**)&pattn, g_attn);
    cudaGetSymbolAddress((void**)&px1,   g_x1);
    cudaGetSymbolAddress((void**)&pact,  g_act);
    cudaGetSymbolAddress((void**)&pwt,   g_wt);
    cudaGetSymbolAddress((void**)&pvt,   g_vT);

    cudaFuncSetAttribute(attn_tc,
        cudaFuncAttributeMaxDynamicSharedMemorySize, ATT_BYTES);
    cudaFuncSetAttribute(tgemm<1536, 512, false, false, false, true>,
        cudaFuncAttributeMaxDynamicSharedMemorySize, GSMEM_B);
    cudaFuncSetAttribute(tgemm<512, 512, true, false, true, false>,
        cudaFuncAttributeMaxDynamicSharedMemorySize, GSMEM_B);
    cudaFuncSetAttribute(tgemm<2048, 512, true, true, false, true>,
        cudaFuncAttributeMaxDynamicSharedMemorySize, GSMEM_B);
    cudaFuncSetAttribute(tgemm<512, 2048, true, false, true, false>,
        cudaFuncAttributeMaxDynamicSharedMemorySize, GSMEM_B);

    // 0. all weight transposes in ONE launch
    transpose_all<<<3072, dim3(32, 8)>>>(qkvw, projw, fc1w, fc2w, pwt);

    // 1. LN1
    ln_kernel<<<ROWS, 128>>>(x, ln1g, ln1b, ph);
    // 2. qkv (ROUND=true)
    tgemm<1536, 512, false, false, false, true><<<dim3(12, 64), 128, GSMEM_B>>>(
        ph, pwt + WT_QKV, nullptr, nullptr, pqkv);
    // 3. V transpose
    vtrans_kernel<<<dim3(64, 2, 32), dim3(32, 8)>>>(pqkv, pvt);
    // 4. attention
    attn_tc<<<dim3(Nseq / 128, Bsz * Hh), 256, ATT_BYTES>>>(
        pqkv, pvt, elev, alpha, pattn);
    // 5. x1 = x + attn @ proj_w + proj_b
    tgemm<512, 512, true, false, true, false><<<dim3(4, 64), 128, GSMEM_B>>>(
        pattn, pwt + WT_PROJ, projb, x, px1);
    // 6. LN2
    ln_kernel<<<ROWS, 128>>>(px1, ln2g, ln2b, ph);
    // 7. act = gelu(h2 @ fc1_w + fc1_b)
    tgemm<2048, 512, true, true, false, true><<<dim3(16, 64), 128, GSMEM_B>>>(
        ph, pwt + WT_FC1, fc1b, nullptr, pact);
    // 8. out = x1 + act @ fc2_w + fc2_b
    tgemm<512, 2048, true, false, true, false><<<dim3(4, 64), 128, GSMEM_B>>>(
        pact, pwt + WT_FC2, fc2b, px1, out);
}

// round 11
// speedup vs baseline: 1.0435x; 1.0435x over previous
#include <cuda_runtime.h>
#include <math.h>
#include <stdint.h>

#define Bsz   4
#define Nseq  2048
#define Dm    512
#define Hh    8
#define HDim  64
#define MLPH  2048
#define ROWS  (Bsz * Nseq)
#define SCALE 0.125f

// ---------------- scratch ----------------
__device__ float g_h[ROWS * Dm];
__device__ float g_qkv[ROWS * 3 * Dm];
__device__ float g_attn[ROWS * Dm];
__device__ float g_x1[ROWS * Dm];
__device__ float g_act[ROWS * MLPH];
__device__ float g_wt[3145728];
__device__ float g_vT[Bsz * Hh * HDim * Nseq];
#define WT_QKV  0
#define WT_PROJ 786432
#define WT_FC1  1048576
#define WT_FC2  2097152

// ---------------- helpers ----------------
__device__ __forceinline__ uint32_t cvt_tf32(float x) {
    uint32_t r; asm("cvt.rna.tf32.f32 %0, %1;" : "=r"(r) : "f"(x)); return r;
}
__device__ __forceinline__ float round_tf32(float x) {
    return __uint_as_float(cvt_tf32(x));
}
__device__ __forceinline__ uint32_t smem_u32(const void* p) {
    return (uint32_t)__cvta_generic_to_shared(p);
}
__device__ __forceinline__ void ldsm4(uint32_t r[4], uint32_t a) {
    asm volatile("ldmatrix.sync.aligned.m8n8.x4.shared.b16 {%0,%1,%2,%3}, [%4];"
        : "=r"(r[0]), "=r"(r[1]), "=r"(r[2]), "=r"(r[3]) : "r"(a));
}
__device__ __forceinline__ void mma8(float d[4], const uint32_t a[4],
                                     uint32_t b0, uint32_t b1) {
    asm volatile(
        "mma.sync.aligned.m16n8k8.row.col.f32.tf32.tf32.f32 "
        "{%0,%1,%2,%3}, {%4,%5,%6,%7}, {%8,%9}, {%0,%1,%2,%3};"
        : "+f"(d[0]), "+f"(d[1]), "+f"(d[2]), "+f"(d[3])
        : "r"(a[0]), "r"(a[1]), "r"(a[2]), "r"(a[3]), "r"(b0), "r"(b1));
}
__device__ __forceinline__ void cpa16(uint32_t dst, const void* src) {
    asm volatile("cp.async.cg.shared.global [%0], [%1], 16;\n"
        :: "r"(dst), "l"(src));
}
#define CP_COMMIT() asm volatile("cp.async.commit_group;\n" ::: "memory")
#define CP_WAIT1()  asm volatile("cp.async.wait_group 1;\n" ::: "memory")
#define CP_WAIT0()  asm volatile("cp.async.wait_group 0;\n" ::: "memory")

// ---------------- merged weight transpose + tf32 round (1 launch) --------
__global__ __launch_bounds__(256) void transpose_all(
    const float* __restrict__ qkvw, const float* __restrict__ projw,
    const float* __restrict__ fc1w, const float* __restrict__ fc2w,
    float* __restrict__ wt)
{
    __shared__ float t[32][33];
    int bid = blockIdx.x;
    const float* in; float* out; int K, N, rel, nx;
    if (bid < 768)       { in = qkvw;  out = wt + WT_QKV;  K = 512;  N = 1536; rel = bid;        nx = 48; }
    else if (bid < 1024) { in = projw; out = wt + WT_PROJ; K = 512;  N = 512;  rel = bid - 768;  nx = 16; }
    else if (bid < 2048) { in = fc1w;  out = wt + WT_FC1;  K = 512;  N = 2048; rel = bid - 1024; nx = 64; }
    else                 { in = fc2w;  out = wt + WT_FC2;  K = 2048; N = 512;  rel = bid - 2048; nx = 16; }
    int n0 = (rel % nx) * 32, k0 = (rel / nx) * 32;
    int tx = threadIdx.x, ty = threadIdx.y;
    #pragma unroll
    for (int j = 0; j < 32; j += 8)
        t[ty + j][tx] = in[(size_t)(k0 + ty + j) * N + n0 + tx];
    __syncthreads();
    #pragma unroll
    for (int j = 0; j < 32; j += 8)
        out[(size_t)(n0 + ty + j) * K + k0 + tx] = round_tf32(t[tx][ty + j]);
}

// ---------------- V transpose ----------------
__global__ __launch_bounds__(256) void vtrans_kernel(
    const float* __restrict__ qkv, float* __restrict__ vT)
{
    __shared__ float t[32][33];
    int bh = blockIdx.z;
    int b = bh >> 3, h = bh & 7;
    int n0 = blockIdx.x * 32, e0 = blockIdx.y * 32;
    int tx = threadIdx.x, ty = threadIdx.y;
    const float* src = qkv + (size_t)(b * Nseq) * (3 * Dm) + 2 * Dm + h * HDim;
    #pragma unroll
    for (int j = 0; j < 32; j += 8)
        t[ty + j][tx] = src[(size_t)(n0 + ty + j) * (3 * Dm) + e0 + tx];
    __syncthreads();
    #pragma unroll
    for (int j = 0; j < 32; j += 8)
        vT[(size_t)(bh * HDim + e0 + ty + j) * Nseq + n0 + tx] = t[tx][ty + j];
}

// ---------------- LayerNorm ----------------
__global__ __launch_bounds__(128) void ln_kernel(
    const float* __restrict__ in, const float* __restrict__ gamma,
    const float* __restrict__ beta, float* __restrict__ out)
{
    int row = blockIdx.x;
    int tid = threadIdx.x;
    const float4* p = (const float4*)(in + (size_t)row * Dm);
    float4 v = p[tid];
    float s  = v.x + v.y + v.z + v.w;
    float ss = v.x * v.x + v.y * v.y + v.z * v.z + v.w * v.w;
    #pragma unroll
    for (int o = 16; o; o >>= 1) {
        s  += __shfl_xor_sync(0xffffffffu, s,  o);
        ss += __shfl_xor_sync(0xffffffffu, ss, o);
    }
    __shared__ float sm[8];
    int w = tid >> 5, lane = tid & 31;
    if (lane == 0) { sm[w] = s; sm[4 + w] = ss; }
    __syncthreads();
    float tot  = sm[0] + sm[1] + sm[2] + sm[3];
    float tot2 = sm[4] + sm[5] + sm[6] + sm[7];
    float mean = tot * (1.0f / Dm);
    float var  = tot2 * (1.0f / Dm) - mean * mean;
    float inv  = rsqrtf(var + 1e-5f);
    float4 g4 = ((const float4*)gamma)[tid];
    float4 b4 = ((const float4*)beta)[tid];
    float4 o;
    o.x = round_tf32((v.x - mean) * inv * g4.x + b4.x);
    o.y = round_tf32((v.y - mean) * inv * g4.y + b4.y);
    o.z = round_tf32((v.z - mean) * inv * g4.z + b4.z);
    o.w = round_tf32((v.w - mean) * inv * g4.w + b4.w);
    ((float4*)(out + (size_t)row * Dm))[tid] = o;
}

// ---------------- TF32 GEMM v5: R9 config + fragment double-buffering ----
// block 128x128, 4 warps (2x2, 64x64 tiles), BK=32, 3-stage cp.async.
// smem layout: phys(row,c16B) = row*128B + ((c ^ (row&7))*16B)  (SW128 atom)
#define GSTG_B  16384
#define GBOFF   49152
#define GSMEM_B 98304

__device__ __forceinline__ float gelu_exact(float x) {
    return 0.5f * x * (1.0f + erff(x * 0.70710678118654752f));
}

template<int N, int K, bool BIAS, bool GELU, bool RES, bool ROUND>
__global__ __launch_bounds__(128, 2) void tgemm(
    const float* __restrict__ A, const float* __restrict__ WT,
    const float* __restrict__ bias, const float* __restrict__ res,
    float* __restrict__ C)
{
    extern __shared__ uint32_t gsm[];
    uint32_t smb = smem_u32(gsm);

    int tid = threadIdx.x, lane = tid & 31, warp = tid >> 5;
    int brow = blockIdx.y * 128, bcol = blockIdx.x * 128;
    int wm = (warp >> 1) * 64, wn = (warp & 1) * 64;
    int la = lane & 7, grp = lane >> 3, g = lane >> 2, t = lane & 3;

    // staging: thread -> (row r0 + 16*i, 16B chunk kc), i = 0..7
    int r0 = tid >> 3, kc = tid & 7;
    const float* Ag = A  + (size_t)(brow + r0) * K + kc * 4;
    const float* Bg = WT + (size_t)(bcol + r0) * K + kc * 4;
    uint32_t dA = smb + (uint32_t)(r0 * 128 + ((kc ^ (r0 & 7)) << 4));
    uint32_t dB = dA + GBOFF;

    // ldsm addresses: 4 A m-tiles, 4 B n-tiles
    uint32_t aAddr[4];
    #pragma unroll
    for (int mi = 0; mi < 4; mi++) {
        int r = wm + mi * 16 + la + (grp & 1) * 8;
        int c = grp >> 1;
        aAddr[mi] = smb + (uint32_t)(r * 128 + ((c ^ (r & 7)) << 4));
    }
    uint32_t bAddr[4];
    #pragma unroll
    for (int nt = 0; nt < 4; nt++) {
        int n = wn + nt * 16 + (lane & 7) + ((lane >> 4) & 1) * 8;
        int c = (lane >> 3) & 1;
        bAddr[nt] = smb + GBOFF + (uint32_t)(n * 128 + ((c ^ (n & 7)) << 4));
    }

    float acc[4][8][4];
    #pragma unroll
    for (int mi = 0; mi < 4; mi++)
        #pragma unroll
        for (int ni = 0; ni < 8; ni++)
            #pragma unroll
            for (int c = 0; c < 4; c++) acc[mi][ni][c] = 0.0f;

    constexpr int iters = K / 32;

    // prologue: prefetch stages 0,1
    #pragma unroll
    for (int p = 0; p < 2; p++) {
        uint32_t oa = dA + p * GSTG_B, ob = dB + p * GSTG_B;
        const float* a = Ag + p * 32;
        const float* w = Bg + p * 32;
        #pragma unroll
        for (int i = 0; i < 8; i++) {
            cpa16(oa + i * 2048, a + (size_t)i * 16 * K);
            cpa16(ob + i * 2048, w + (size_t)i * 16 * K);
        }
        CP_COMMIT();
    }

    #pragma unroll 1
    for (int it = 0; it < iters; ++it) {
        CP_WAIT1();
        __syncthreads();
        if (it + 2 < iters) {
            uint32_t so = (uint32_t)(((it + 2) % 3) * GSTG_B);
            const float* a = Ag + (it + 2) * 32;
            const float* w = Bg + (it + 2) * 32;
            #pragma unroll
            for (int i = 0; i < 8; i++) {
                cpa16(dA + so + i * 2048, a + (size_t)i * 16 * K);
                cpa16(dB + so + i * 2048, w + (size_t)i * 16 * K);
            }
        }
        CP_COMMIT();

        uint32_t so = (uint32_t)((it % 3) * GSTG_B);

        // fragment double-buffer across the 4 k8 sub-steps
        uint32_t af[2][4][4], bf[2][4][4];
        #pragma unroll
        for (int mi = 0; mi < 4; mi++) ldsm4(af[0][mi], aAddr[mi] + so);
        #pragma unroll
        for (int nt = 0; nt < 4; nt++) ldsm4(bf[0][nt], bAddr[nt] + so);

        #pragma unroll
        for (int ks = 0; ks < 4; ks++) {
            int cur = ks & 1, nxt = cur ^ 1;
            if (ks < 3) {
                uint32_t kx = (uint32_t)((ks + 1) << 5);
                #pragma unroll
                for (int mi = 0; mi < 4; mi++)
                    ldsm4(af[nxt][mi], (aAddr[mi] + so) ^ kx);
                #pragma unroll
                for (int nt = 0; nt < 4; nt++)
                    ldsm4(bf[nxt][nt], (bAddr[nt] + so) ^ kx);
            }
            #pragma unroll
            for (int nt = 0; nt < 4; nt++) {
                #pragma unroll
                for (int mi = 0; mi < 4; mi++) {
                    mma8(acc[mi][nt * 2],     af[cur][mi], bf[cur][nt][0], bf[cur][nt][1]);
                    mma8(acc[mi][nt * 2 + 1], af[cur][mi], bf[cur][nt][2], bf[cur][nt][3]);
                }
            }
        }
    }

    // epilogue
    #pragma unroll
    for (int mi = 0; mi < 4; mi++) {
        int r0e = brow + wm + mi * 16 + g;
        #pragma unroll
        for (int ni = 0; ni < 8; ni++) {
            int col = bcol + wn + ni * 8 + t * 2;
            float2 v0 = {acc[mi][ni][0], acc[mi][ni][1]};
            float2 v1 = {acc[mi][ni][2], acc[mi][ni][3]};
            if (BIAS) {
                float2 bb = *(const float2*)&bias[col];
                v0.x += bb.x; v0.y += bb.y; v1.x += bb.x; v1.y += bb.y;
            }
            if (GELU) {
                v0.x = gelu_exact(v0.x); v0.y = gelu_exact(v0.y);
                v1.x = gelu_exact(v1.x); v1.y = gelu_exact(v1.y);
            }
            if (RES) {
                float2 q0 = *(const float2*)&res[(size_t)r0e * N + col];
                float2 q1 = *(const float2*)&res[(size_t)(r0e + 8) * N + col];
                v0.x += q0.x; v0.y += q0.y; v1.x += q1.x; v1.y += q1.y;
            }
            if (ROUND) {
                v0.x = round_tf32(v0.x); v0.y = round_tf32(v0.y);
                v1.x = round_tf32(v1.x); v1.y = round_tf32(v1.y);
            }
            *(float2*)&C[(size_t)r0e * N + col] = v0;
            *(float2*)&C[(size_t)(r0e + 8) * N + col] = v1;
        }
    }
}

// ---------------- TF32 flash attention (unchanged) ----------------
#define KPW      68
#define OFF_QP   0
#define OFF_K    8704
#define OFF_V    17408
#define OFF_EK   26112
#define ATT_WORDS 26240
#define ATT_BYTES (ATT_WORDS * 4)
#define KVSTG    4352

__device__ __forceinline__ float bias_f(float eq, float ek, float alpha) {
    float diff = (ek - eq) * 1e-3f;
    float b = -alpha * fmaxf(diff, 0.0f);
    return fminf(fmaxf(b, -10.0f), 0.0f);
}

__global__ __launch_bounds__(256, 2) void attn_tc(
    const float* __restrict__ qkv, const float* __restrict__ vT,
    const float* __restrict__ elev, const float* __restrict__ alpha_p,
    float* __restrict__ out)
{
    extern __shared__ uint32_t dsm[];
    uint32_t smb = smem_u32(dsm);
    float* sEK = (float*)(dsm + OFF_EK);

    int bh = blockIdx.y;
    int b = bh >> 3, h = bh & 7;
    int q0 = blockIdx.x * 128;
    int tid = threadIdx.x, lane = tid & 31, warp = tid >> 5;
    int la = lane & 7, grp = lane >> 3, g = lane >> 2, t = lane & 3;
    float alpha = alpha_p[0];
    const float* eb = elev + b * Nseq;
    const float* qbase = qkv + ((size_t)(b * Nseq + q0)) * (3 * Dm) + h * HDim;
    const float* kvb   = qkv + ((size_t)(b * Nseq)) * (3 * Dm) + Dm + h * HDim;
    const float* vtb   = vT + (size_t)(bh * HDim) * Nseq;

    #pragma unroll
    for (int i = 0; i < 8; i++) {
        int idx = tid + i * 256;
        int r = idx >> 4, c4 = (idx & 15) * 4;
        cpa16(smb + (uint32_t)(OFF_QP + r * KPW + c4) * 4u,
              qbase + (size_t)r * (3 * Dm) + c4);
    }
    #pragma unroll
    for (int i = 0; i < 4; i++) {
        int idx = tid + i * 256;
        int r = idx >> 4, c4 = (idx & 15) * 4;
        cpa16(smb + (uint32_t)(OFF_K + r * KPW + c4) * 4u,
              kvb + (size_t)r * (3 * Dm) + c4);
        cpa16(smb + (uint32_t)(OFF_V + r * KPW + c4) * 4u,
              vtb + (size_t)r * Nseq + c4);
    }
    if (tid < 64) sEK[tid] = eb[tid];
    CP_COMMIT();
    CP_WAIT0();
    __syncthreads();

    int qr0 = warp * 16;
    uint32_t aAddr = smb +
        (uint32_t)(OFF_QP + (qr0 + la + (grp & 1) * 8) * KPW + (grp >> 1) * 4) * 4u;
    uint32_t qf[8][4];
    #pragma unroll
    for (int kc = 0; kc < 8; kc++) ldsm4(qf[kc], aAddr + kc * 32);

    float eq0 = eb[q0 + qr0 + g];
    float eq1 = eb[q0 + qr0 + g + 8];

    uint32_t bAddrK[4], bAddrV[4];
    #pragma unroll
    for (int nt = 0; nt < 4; nt++) {
        int r = nt * 16 + la + (grp >> 1) * 8;
        bAddrK[nt] = smb + (uint32_t)(OFF_K + r * KPW + (grp & 1) * 4) * 4u;
        bAddrV[nt] = smb + (uint32_t)(OFF_V + r * KPW + (grp & 1) * 4) * 4u;
    }

    float O[8][4];
    #pragma unroll
    for (int e = 0; e < 8; e++)
        O[e][0] = O[e][1] = O[e][2] = O[e][3] = 0.0f;
    float mi0 = -1e30f, mi1 = -1e30f, li0 = 0.0f, li1 = 0.0f;

    #pragma unroll 1
    for (int tt = 0; tt < Nseq / 64; tt++) {
        if (tt) { CP_WAIT0(); __syncthreads(); }
        if (tt + 1 < Nseq / 64) {
            int bufn = (tt + 1) & 1;
            int k0n = (tt + 1) * 64;
            const float* kb = kvb + (size_t)k0n * (3 * Dm);
            #pragma unroll
            for (int i = 0; i < 4; i++) {
                int idx = tid + i * 256;
                int r = idx >> 4, c4 = (idx & 15) * 4;
                cpa16(smb + (uint32_t)(OFF_K + bufn * KVSTG + r * KPW + c4) * 4u,
                      kb + (size_t)r * (3 * Dm) + c4);
                cpa16(smb + (uint32_t)(OFF_V + bufn * KVSTG + r * KPW + c4) * 4u,
                      vtb + (size_t)r * Nseq + k0n + c4);
            }
            if (tid < 64) sEK[bufn * 64 + tid] = eb[k0n + tid];
        }
        CP_COMMIT();

        int buf = tt & 1;
        uint32_t bOff = (uint32_t)(buf * KVSTG) * 4u;

        float S[8][4];
        #pragma unroll
        for (int nt = 0; nt < 8; nt++)
            S[nt][0] = S[nt][1] = S[nt][2] = S[nt][3] = 0.0f;
        #pragma unroll
        for (int kc = 0; kc < 8; kc++) {
            #pragma unroll
            for (int nt4 = 0; nt4 < 4; nt4++) {
                uint32_t bf[4];
                ldsm4(bf, bAddrK[nt4] + bOff + kc * 32);
                mma8(S[nt4 * 2], qf[kc], bf[0], bf[1]);
                mma8(S[nt4 * 2 + 1], qf[kc], bf[2], bf[3]);
            }
        }

        float rm0 = -1e30f, rm1 = -1e30f;
        #pragma unroll
        for (int nt = 0; nt < 8; nt++) {
            float ek0 = sEK[buf * 64 + nt * 8 + t * 2];
            float ek1 = sEK[buf * 64 + nt * 8 + t * 2 + 1];
            S[nt][0] = S[nt][0] * SCALE + bias_f(eq0, ek0, alpha);
            S[nt][1] = S[nt][1] * SCALE + bias_f(eq0, ek1, alpha);
            S[nt][2] = S[nt][2] * SCALE + bias_f(eq1, ek0, alpha);
            S[nt][3] = S[nt][3] * SCALE + bias_f(eq1, ek1, alpha);
            rm0 = fmaxf(rm0, fmaxf(S[nt][0], S[nt][1]));
            rm1 = fmaxf(rm1, fmaxf(S[nt][2], S[nt][3]));
        }
        rm0 = fmaxf(rm0, __shfl_xor_sync(0xffffffffu, rm0, 1));
        rm0 = fmaxf(rm0, __shfl_xor_sync(0xffffffffu, rm0, 2));
        rm1 = fmaxf(rm1, __shfl_xor_sync(0xffffffffu, rm1, 1));
        rm1 = fmaxf(rm1, __shfl_xor_sync(0xffffffffu, rm1, 2));
        float mn0 = fmaxf(mi0, rm0), mn1 = fmaxf(mi1, rm1);
        float c0 = __expf(mi0 - mn0), c1 = __expf(mi1 - mn1);
        mi0 = mn0; mi1 = mn1;
        float rs0 = 0.0f, rs1 = 0.0f;
        #pragma unroll
        for (int nt = 0; nt < 8; nt++) {
            S[nt][0] = __expf(S[nt][0] - mn0); rs0 += S[nt][0];
            S[nt][1] = __expf(S[nt][1] - mn0); rs0 += S[nt][1];
            S[nt][2] = __expf(S[nt][2] - mn1); rs1 += S[nt][2];
            S[nt][3] = __expf(S[nt][3] - mn1); rs1 += S[nt][3];
        }
        rs0 += __shfl_xor_sync(0xffffffffu, rs0, 1);
        rs0 += __shfl_xor_sync(0xffffffffu, rs0, 2);
        rs1 += __shfl_xor_sync(0xffffffffu, rs1, 1);
        rs1 += __shfl_xor_sync(0xffffffffu, rs1, 2);
        li0 = li0 * c0 + rs0;
        li1 = li1 * c1 + rs1;
        #pragma unroll
        for (int e = 0; e < 8; e++) {
            O[e][0] *= c0; O[e][1] *= c0; O[e][2] *= c1; O[e][3] *= c1;
        }

        #pragma unroll
        for (int nt = 0; nt < 8; nt++) {
            uint32_t* p0 = &dsm[OFF_QP + (qr0 + g) * KPW + nt * 8 + t * 2];
            uint32_t* p1 = &dsm[OFF_QP + (qr0 + 8 + g) * KPW + nt * 8 + t * 2];
            p0[0] = cvt_tf32(S[nt][0]); p0[1] = cvt_tf32(S[nt][1]);
            p1[0] = cvt_tf32(S[nt][2]); p1[1] = cvt_tf32(S[nt][3]);
        }
        __syncwarp();

        #pragma unroll
        for (int kc = 0; kc < 8; kc++) {
            uint32_t pf[4];
            ldsm4(pf, aAddr + kc * 32);
            #pragma unroll
            for (int nt4 = 0; nt4 < 4; nt4++) {
                uint32_t bf[4];
                ldsm4(bf, bAddrV[nt4] + bOff + kc * 32);
                mma8(O[nt4 * 2],     pf, bf[0], bf[1]);
                mma8(O[nt4 * 2 + 1], pf, bf[2], bf[3]);
            }
        }
    }

    float inv0 = 1.0f / li0, inv1 = 1.0f / li1;
    int row0 = b * Nseq + q0 + qr0 + g;
    #pragma unroll
    for (int e = 0; e < 8; e++) {
        int col = h * HDim + e * 8 + t * 2;
        float2 o0 = {round_tf32(O[e][0] * inv0), round_tf32(O[e][1] * inv0)};
        float2 o1 = {round_tf32(O[e][2] * inv1), round_tf32(O[e][3] * inv1)};
        *(float2*)&out[(size_t)row0 * Dm + col] = o0;
        *(float2*)&out[(size_t)(row0 + 8) * Dm + col] = o1;
    }
}

// ---------------- launch ----------------
extern "C" void kernel_launch(void* const* d_in, const int* in_sizes, int n_in,
                              void* d_out, int out_size)
{
    const float* x     = (const float*)d_in[0];
    const float* elev  = (const float*)d_in[1];
    const float* ln1g  = (const float*)d_in[2];
    const float* ln1b  = (const float*)d_in[3];
    const float* qkvw  = (const float*)d_in[4];
    const float* alpha = (const float*)d_in[5];
    const float* projw = (const float*)d_in[6];
    const float* projb = (const float*)d_in[7];
    const float* ln2g  = (const float*)d_in[8];
    const float* ln2b  = (const float*)d_in[9];
    const float* fc1w  = (const float*)d_in[10];
    const float* fc1b  = (const float*)d_in[11];
    const float* fc2w  = (const float*)d_in[12];
    const float* fc2b  = (const float*)d_in[13];
    float* out = (float*)d_out;

    float *ph, *pqkv, *pattn, *px1, *pact, *pwt, *pvt;
    cudaGetSymbolAddress((void**)&ph,    g_h);
    cudaGetSymbolAddress((void**)&pqkv,  g_qkv);
    cudaGetSymbolAddress((void**)&pattn, g_attn);
    cudaGetSymbolAddress((void**)&px1,   g_x1);
    cudaGetSymbolAddress((void**)&pact,  g_act);
    cudaGetSymbolAddress((void**)&pwt,   g_wt);
    cudaGetSymbolAddress((void**)&pvt,   g_vT);

    cudaFuncSetAttribute(attn_tc,
        cudaFuncAttributeMaxDynamicSharedMemorySize, ATT_BYTES);
    cudaFuncSetAttribute(tgemm<1536, 512, false, false, false, true>,
        cudaFuncAttributeMaxDynamicSharedMemorySize, GSMEM_B);
    cudaFuncSetAttribute(tgemm<512, 512, true, false, true, false>,
        cudaFuncAttributeMaxDynamicSharedMemorySize, GSMEM_B);
    cudaFuncSetAttribute(tgemm<2048, 512, true, true, false, true>,
        cudaFuncAttributeMaxDynamicSharedMemorySize, GSMEM_B);
    cudaFuncSetAttribute(tgemm<512, 2048, true, false, true, false>,
        cudaFuncAttributeMaxDynamicSharedMemorySize, GSMEM_B);

    // 0. all weight transposes in ONE launch
    transpose_all<<<3072, dim3(32, 8)>>>(qkvw, projw, fc1w, fc2w, pwt);

    // 1. LN1
    ln_kernel<<<ROWS, 128>>>(x, ln1g, ln1b, ph);
    // 2. qkv (ROUND=true)
    tgemm<1536, 512, false, false, false, true><<<dim3(12, 64), 128, GSMEM_B>>>(
        ph, pwt + WT_QKV, nullptr, nullptr, pqkv);
    // 3. V transpose
    vtrans_kernel<<<dim3(64, 2, 32), dim3(32, 8)>>>(pqkv, pvt);
    // 4. attention
    attn_tc<<<dim3(Nseq / 128, Bsz * Hh), 256, ATT_BYTES>>>(
        pqkv, pvt, elev, alpha, pattn);
    // 5. x1 = x + attn @ proj_w + proj_b
    tgemm<512, 512, true, false, true, false><<<dim3(4, 64), 128, GSMEM_B>>>(
        pattn, pwt + WT_PROJ, projb, x, px1);
    // 6. LN2
    ln_kernel<<<ROWS, 128>>>(px1, ln2g, ln2b, ph);
    // 7. act = gelu(h2 @ fc1_w + fc1_b)
    tgemm<2048, 512, true, true, false, true><<<dim3(16, 64), 128, GSMEM_B>>>(
        ph, pwt + WT_FC1, fc1b, nullptr, pact);
    // 8. out = x1 + act @ fc2_w + fc2_b
    tgemm<512, 2048, true, false, true, false><<<dim3(4, 64), 128, GSMEM_B>>>(
        pact, pwt + WT_FC2, fc2b, px1, out);
}

// round 12
// speedup vs baseline: 1.7481x; 1.6752x over previous
#include <cuda_runtime.h>
#include <cuda_fp16.h>
#include <math.h>
#include <stdint.h>

#define Bsz   4
#define Nseq  2048
#define Dm    512
#define Hh    8
#define HDim  64
#define MLPH  2048
#define ROWS  (Bsz * Nseq)
#define SCALE 0.125f

// ---------------- scratch ----------------
__device__ __half g_h[ROWS * Dm];
__device__ __half g_qkv[ROWS * 3 * Dm];
__device__ __half g_attn[ROWS * Dm];
__device__ float  g_x1[ROWS * Dm];
__device__ __half g_act[ROWS * MLPH];
__device__ __half g_wt[3145728];
__device__ __half g_vT[Bsz * Hh * HDim * Nseq];
#define WT_QKV  0
#define WT_PROJ 786432
#define WT_FC1  1048576
#define WT_FC2  2097152

// ---------------- helpers ----------------
__device__ __forceinline__ uint32_t smem_u32(const void* p) {
    return (uint32_t)__cvta_generic_to_shared(p);
}
__device__ __forceinline__ void ldsm4(uint32_t r[4], uint32_t a) {
    asm volatile("ldmatrix.sync.aligned.m8n8.x4.shared.b16 {%0,%1,%2,%3}, [%4];"
        : "=r"(r[0]), "=r"(r[1]), "=r"(r[2]), "=r"(r[3]) : "r"(a));
}
__device__ __forceinline__ void mma16(float d[4], const uint32_t a[4],
                                      uint32_t b0, uint32_t b1) {
    asm volatile(
        "mma.sync.aligned.m16n8k16.row.col.f32.f16.f16.f32 "
        "{%0,%1,%2,%3}, {%4,%5,%6,%7}, {%8,%9}, {%0,%1,%2,%3};"
        : "+f"(d[0]), "+f"(d[1]), "+f"(d[2]), "+f"(d[3])
        : "r"(a[0]), "r"(a[1]), "r"(a[2]), "r"(a[3]), "r"(b0), "r"(b1));
}
__device__ __forceinline__ void cpa16(uint32_t dst, const void* src) {
    asm volatile("cp.async.cg.shared.global [%0], [%1], 16;\n"
        :: "r"(dst), "l"(src));
}
#define CP_COMMIT() asm volatile("cp.async.commit_group;\n" ::: "memory")
#define CP_WAIT1()  asm volatile("cp.async.wait_group 1;\n" ::: "memory")
#define CP_WAIT0()  asm volatile("cp.async.wait_group 0;\n" ::: "memory")

// ---------------- merged weight transpose -> fp16 [n][k] ----------------
__global__ __launch_bounds__(256) void transpose_all(
    const float* __restrict__ qkvw, const float* __restrict__ projw,
    const float* __restrict__ fc1w, const float* __restrict__ fc2w,
    __half* __restrict__ wt)
{
    __shared__ float t[32][33];
    int bid = blockIdx.x;
    const float* in; __half* out; int K, N, rel, nx;
    if (bid < 768)       { in = qkvw;  out = wt + WT_QKV;  K = 512;  N = 1536; rel = bid;        nx = 48; }
    else if (bid < 1024) { in = projw; out = wt + WT_PROJ; K = 512;  N = 512;  rel = bid - 768;  nx = 16; }
    else if (bid < 2048) { in = fc1w;  out = wt + WT_FC1;  K = 512;  N = 2048; rel = bid - 1024; nx = 64; }
    else                 { in = fc2w;  out = wt + WT_FC2;  K = 2048; N = 512;  rel = bid - 2048; nx = 16; }
    int n0 = (rel % nx) * 32, k0 = (rel / nx) * 32;
    int tx = threadIdx.x, ty = threadIdx.y;
    #pragma unroll
    for (int j = 0; j < 32; j += 8)
        t[ty + j][tx] = in[(size_t)(k0 + ty + j) * N + n0 + tx];
    __syncthreads();
    #pragma unroll
    for (int j = 0; j < 32; j += 8)
        out[(size_t)(n0 + ty + j) * K + k0 + tx] = __float2half_rn(t[tx][ty + j]);
}

// ---------------- V transpose (half) ----------------
__global__ __launch_bounds__(256) void vtrans_kernel(
    const __half* __restrict__ qkv, __half* __restrict__ vT)
{
    __shared__ __half t[32][33];
    int bh = blockIdx.z;
    int b = bh >> 3, h = bh & 7;
    int n0 = blockIdx.x * 32, e0 = blockIdx.y * 32;
    int tx = threadIdx.x, ty = threadIdx.y;
    const __half* src = qkv + (size_t)(b * Nseq) * (3 * Dm) + 2 * Dm + h * HDim;
    #pragma unroll
    for (int j = 0; j < 32; j += 8)
        t[ty + j][tx] = src[(size_t)(n0 + ty + j) * (3 * Dm) + e0 + tx];
    __syncthreads();
    #pragma unroll
    for (int j = 0; j < 32; j += 8)
        vT[(size_t)(bh * HDim + e0 + ty + j) * Nseq + n0 + tx] = t[tx][ty + j];
}

// ---------------- LayerNorm (fp32 in -> fp16 out) ----------------
__global__ __launch_bounds__(128) void ln_kernel(
    const float* __restrict__ in, const float* __restrict__ gamma,
    const float* __restrict__ beta, __half* __restrict__ out)
{
    int row = blockIdx.x;
    int tid = threadIdx.x;
    const float4* p = (const float4*)(in + (size_t)row * Dm);
    float4 v = p[tid];
    float s  = v.x + v.y + v.z + v.w;
    float ss = v.x * v.x + v.y * v.y + v.z * v.z + v.w * v.w;
    #pragma unroll
    for (int o = 16; o; o >>= 1) {
        s  += __shfl_xor_sync(0xffffffffu, s,  o);
        ss += __shfl_xor_sync(0xffffffffu, ss, o);
    }
    __shared__ float sm[8];
    int w = tid >> 5, lane = tid & 31;
    if (lane == 0) { sm[w] = s; sm[4 + w] = ss; }
    __syncthreads();
    float tot  = sm[0] + sm[1] + sm[2] + sm[3];
    float tot2 = sm[4] + sm[5] + sm[6] + sm[7];
    float mean = tot * (1.0f / Dm);
    float var  = tot2 * (1.0f / Dm) - mean * mean;
    float inv  = rsqrtf(var + 1e-5f);
    float4 g4 = ((const float4*)gamma)[tid];
    float4 b4 = ((const float4*)beta)[tid];
    __half2* op = (__half2*)(out + (size_t)row * Dm);
    op[tid * 2]     = __floats2half2_rn((v.x - mean) * inv * g4.x + b4.x,
                                        (v.y - mean) * inv * g4.y + b4.y);
    op[tid * 2 + 1] = __floats2half2_rn((v.z - mean) * inv * g4.z + b4.z,
                                        (v.w - mean) * inv * g4.w + b4.w);
}

// ---------------- FP16 GEMM: 128x128 tile, 4 warps (64x64), BK=64 halfs --
// smem row = 64 halfs = 128B, SW128 atom swizzle: phys16B = c ^ (row&7).
#define GSTG_B  16384
#define GBOFF   49152
#define GSMEM_B 98304

__device__ __forceinline__ float gelu_exact(float x) {
    return 0.5f * x * (1.0f + erff(x * 0.70710678118654752f));
}

template<int N, int K, bool BIAS, bool GELU, bool RES, bool HOUT>
__global__ __launch_bounds__(128, 2) void tgemm(
    const __half* __restrict__ A, const __half* __restrict__ WT,
    const float* __restrict__ bias, const float* __restrict__ res,
    void* __restrict__ Cv)
{
    extern __shared__ uint32_t gsm[];
    uint32_t smb = smem_u32(gsm);

    int tid = threadIdx.x, lane = tid & 31, warp = tid >> 5;
    int brow = blockIdx.y * 128, bcol = blockIdx.x * 128;
    int wm = (warp >> 1) * 64, wn = (warp & 1) * 64;
    int la = lane & 7, grp = lane >> 3, g = lane >> 2, t = lane & 3;

    // staging: row r0 (+16*i), 16B chunk kc (8 halfs)
    int r0 = tid >> 3, kc = tid & 7;
    const __half* Ag = A  + (size_t)(brow + r0) * K + kc * 8;
    const __half* Bg = WT + (size_t)(bcol + r0) * K + kc * 8;
    uint32_t dA = smb + (uint32_t)(r0 * 128 + ((kc ^ (r0 & 7)) << 4));
    uint32_t dB = dA + GBOFF;

    uint32_t aAddr[4];
    #pragma unroll
    for (int mi = 0; mi < 4; mi++) {
        int r = wm + mi * 16 + la + (grp & 1) * 8;
        int c = grp >> 1;
        aAddr[mi] = smb + (uint32_t)(r * 128 + ((c ^ (r & 7)) << 4));
    }
    uint32_t bAddr[4];
    #pragma unroll
    for (int nt = 0; nt < 4; nt++) {
        int n = wn + nt * 16 + (lane & 7) + ((lane >> 4) & 1) * 8;
        int c = (lane >> 3) & 1;
        bAddr[nt] = smb + GBOFF + (uint32_t)(n * 128 + ((c ^ (n & 7)) << 4));
    }

    float acc[4][8][4];
    #pragma unroll
    for (int mi = 0; mi < 4; mi++)
        #pragma unroll
        for (int ni = 0; ni < 8; ni++)
            #pragma unroll
            for (int c = 0; c < 4; c++) acc[mi][ni][c] = 0.0f;

    constexpr int iters = K / 64;

    #pragma unroll
    for (int p = 0; p < 2; p++) {
        uint32_t oa = dA + p * GSTG_B, ob = dB + p * GSTG_B;
        const __half* a = Ag + p * 64;
        const __half* w = Bg + p * 64;
        #pragma unroll
        for (int i = 0; i < 8; i++) {
            cpa16(oa + i * 2048, a + (size_t)i * 16 * K);
            cpa16(ob + i * 2048, w + (size_t)i * 16 * K);
        }
        CP_COMMIT();
    }

    #pragma unroll 1
    for (int it = 0; it < iters; ++it) {
        CP_WAIT1();
        __syncthreads();
        if (it + 2 < iters) {
            uint32_t so = (uint32_t)(((it + 2) % 3) * GSTG_B);
            const __half* a = Ag + (it + 2) * 64;
            const __half* w = Bg + (it + 2) * 64;
            #pragma unroll
            for (int i = 0; i < 8; i++) {
                cpa16(dA + so + i * 2048, a + (size_t)i * 16 * K);
                cpa16(dB + so + i * 2048, w + (size_t)i * 16 * K);
            }
        }
        CP_COMMIT();

        uint32_t so = (uint32_t)((it % 3) * GSTG_B);

        uint32_t af[2][4][4], bf[2][4][4];
        #pragma unroll
        for (int mi = 0; mi < 4; mi++) ldsm4(af[0][mi], aAddr[mi] + so);
        #pragma unroll
        for (int nt = 0; nt < 4; nt++) ldsm4(bf[0][nt], bAddr[nt] + so);

        #pragma unroll
        for (int ks = 0; ks < 4; ks++) {           // 4 k16 substeps
            int cur = ks & 1, nxt = cur ^ 1;
            if (ks < 3) {
                uint32_t kx = (uint32_t)((ks + 1) << 5);
                #pragma unroll
                for (int mi = 0; mi < 4; mi++)
                    ldsm4(af[nxt][mi], (aAddr[mi] + so) ^ kx);
                #pragma unroll
                for (int nt = 0; nt < 4; nt++)
                    ldsm4(bf[nxt][nt], (bAddr[nt] + so) ^ kx);
            }
            #pragma unroll
            for (int nt = 0; nt < 4; nt++) {
                #pragma unroll
                for (int mi = 0; mi < 4; mi++) {
                    mma16(acc[mi][nt * 2],     af[cur][mi], bf[cur][nt][0], bf[cur][nt][1]);
                    mma16(acc[mi][nt * 2 + 1], af[cur][mi], bf[cur][nt][2], bf[cur][nt][3]);
                }
            }
        }
    }

    // epilogue
    #pragma unroll
    for (int mi = 0; mi < 4; mi++) {
        int r0e = brow + wm + mi * 16 + g;
        #pragma unroll
        for (int ni = 0; ni < 8; ni++) {
            int col = bcol + wn + ni * 8 + t * 2;
            float2 v0 = {acc[mi][ni][0], acc[mi][ni][1]};
            float2 v1 = {acc[mi][ni][2], acc[mi][ni][3]};
            if (BIAS) {
                float2 bb = *(const float2*)&bias[col];
                v0.x += bb.x; v0.y += bb.y; v1.x += bb.x; v1.y += bb.y;
            }
            if (GELU) {
                v0.x = gelu_exact(v0.x); v0.y = gelu_exact(v0.y);
                v1.x = gelu_exact(v1.x); v1.y = gelu_exact(v1.y);
            }
            if (RES) {
                float2 q0 = *(const float2*)&res[(size_t)r0e * N + col];
                float2 q1 = *(const float2*)&res[(size_t)(r0e + 8) * N + col];
                v0.x += q0.x; v0.y += q0.y; v1.x += q1.x; v1.y += q1.y;
            }
            if (HOUT) {
                __half* C = (__half*)Cv;
                *(__half2*)&C[(size_t)r0e * N + col]       = __floats2half2_rn(v0.x, v0.y);
                *(__half2*)&C[(size_t)(r0e + 8) * N + col] = __floats2half2_rn(v1.x, v1.y);
            } else {
                float* C = (float*)Cv;
                *(float2*)&C[(size_t)r0e * N + col] = v0;
                *(float2*)&C[(size_t)(r0e + 8) * N + col] = v1;
            }
        }
    }
}

// ---------------- FP16 flash attention ----------------
// 128 q-rows, 256 thr, half tiles with stride 72 halfs (9x16B, odd -> conflict-free)
#define KPWH   72
#define AOFF_QP 0
#define AOFF_K  9216
#define AOFF_V  18432
#define AOFF_EK 27648           // half index; cast to float*
#define ATT_BYTES 55808
#define KVSTGH  4608

__device__ __forceinline__ float bias_f(float eq, float ek, float alpha) {
    float diff = (ek - eq) * 1e-3f;
    float b = -alpha * fmaxf(diff, 0.0f);
    return fminf(fmaxf(b, -10.0f), 0.0f);
}

__global__ __launch_bounds__(256, 2) void attn_tc(
    const __half* __restrict__ qkv, const __half* __restrict__ vT,
    const float* __restrict__ elev, const float* __restrict__ alpha_p,
    __half* __restrict__ out)
{
    extern __shared__ __half dsm[];
    uint32_t smb = smem_u32(dsm);
    float* sEK = (float*)(dsm + AOFF_EK);

    int bh = blockIdx.y;
    int b = bh >> 3, h = bh & 7;
    int q0 = blockIdx.x * 128;
    int tid = threadIdx.x, lane = tid & 31, warp = tid >> 5;
    int la = lane & 7, grp = lane >> 3, g = lane >> 2, t = lane & 3;
    float alpha = alpha_p[0];
    const float* eb = elev + b * Nseq;
    const __half* qbase = qkv + ((size_t)(b * Nseq + q0)) * (3 * Dm) + h * HDim;
    const __half* kvb   = qkv + ((size_t)(b * Nseq)) * (3 * Dm) + Dm + h * HDim;
    const __half* vtb   = vT + (size_t)(bh * HDim) * Nseq;

    // stage Q (1024 16B chunks) + K/V tile 0 (512 chunks each)
    #pragma unroll
    for (int i = 0; i < 4; i++) {
        int idx = tid + i * 256;
        int r = idx >> 3, c8 = (idx & 7) * 8;
        cpa16(smb + (uint32_t)(AOFF_QP + r * KPWH + c8) * 2u,
              qbase + (size_t)r * (3 * Dm) + c8);
    }
    #pragma unroll
    for (int i = 0; i < 2; i++) {
        int idx = tid + i * 256;
        int r = idx >> 3, c8 = (idx & 7) * 8;
        cpa16(smb + (uint32_t)(AOFF_K + r * KPWH + c8) * 2u,
              kvb + (size_t)r * (3 * Dm) + c8);
        cpa16(smb + (uint32_t)(AOFF_V + r * KPWH + c8) * 2u,
              vtb + (size_t)r * Nseq + c8);
    }
    if (tid < 64) sEK[tid] = eb[tid];
    CP_COMMIT();
    CP_WAIT0();
    __syncthreads();

    int qr0 = warp * 16;
    uint32_t aAddr = smb +
        (uint32_t)(AOFF_QP + (qr0 + la + (grp & 1) * 8) * KPWH + (grp >> 1) * 8) * 2u;
    uint32_t qf[4][4];
    #pragma unroll
    for (int kc = 0; kc < 4; kc++) ldsm4(qf[kc], aAddr + kc * 32);

    float eq0 = eb[q0 + qr0 + g];
    float eq1 = eb[q0 + qr0 + g + 8];

    uint32_t bAddrK[4], bAddrV[4];
    #pragma unroll
    for (int nt = 0; nt < 4; nt++) {
        int r = nt * 16 + la + (grp >> 1) * 8;
        bAddrK[nt] = smb + (uint32_t)(AOFF_K + r * KPWH + (grp & 1) * 8) * 2u;
        bAddrV[nt] = smb + (uint32_t)(AOFF_V + r * KPWH + (grp & 1) * 8) * 2u;
    }

    float O[8][4];
    #pragma unroll
    for (int e = 0; e < 8; e++)
        O[e][0] = O[e][1] = O[e][2] = O[e][3] = 0.0f;
    float mi0 = -1e30f, mi1 = -1e30f, li0 = 0.0f, li1 = 0.0f;

    #pragma unroll 1
    for (int tt = 0; tt < Nseq / 64; tt++) {
        if (tt) { CP_WAIT0(); __syncthreads(); }
        if (tt + 1 < Nseq / 64) {
            int bufn = (tt + 1) & 1;
            int k0n = (tt + 1) * 64;
            const __half* kb = kvb + (size_t)k0n * (3 * Dm);
            #pragma unroll
            for (int i = 0; i < 2; i++) {
                int idx = tid + i * 256;
                int r = idx >> 3, c8 = (idx & 7) * 8;
                cpa16(smb + (uint32_t)(AOFF_K + bufn * KVSTGH + r * KPWH + c8) * 2u,
                      kb + (size_t)r * (3 * Dm) + c8);
                cpa16(smb + (uint32_t)(AOFF_V + bufn * KVSTGH + r * KPWH + c8) * 2u,
                      vtb + (size_t)r * Nseq + k0n + c8);
            }
            if (tid < 64) sEK[bufn * 64 + tid] = eb[k0n + tid];
        }
        CP_COMMIT();

        int buf = tt & 1;
        uint32_t bOff = (uint32_t)(buf * KVSTGH) * 2u;

        // S = Q K^T
        float S[8][4];
        #pragma unroll
        for (int nt = 0; nt < 8; nt++)
            S[nt][0] = S[nt][1] = S[nt][2] = S[nt][3] = 0.0f;
        #pragma unroll
        for (int kc = 0; kc < 4; kc++) {
            #pragma unroll
            for (int nt4 = 0; nt4 < 4; nt4++) {
                uint32_t bf[4];
                ldsm4(bf, bAddrK[nt4] + bOff + kc * 32);
                mma16(S[nt4 * 2],     qf[kc], bf[0], bf[1]);
                mma16(S[nt4 * 2 + 1], qf[kc], bf[2], bf[3]);
            }
        }

        float rm0 = -1e30f, rm1 = -1e30f;
        #pragma unroll
        for (int nt = 0; nt < 8; nt++) {
            float ek0 = sEK[buf * 64 + nt * 8 + t * 2];
            float ek1 = sEK[buf * 64 + nt * 8 + t * 2 + 1];
            S[nt][0] = S[nt][0] * SCALE + bias_f(eq0, ek0, alpha);
            S[nt][1] = S[nt][1] * SCALE + bias_f(eq0, ek1, alpha);
            S[nt][2] = S[nt][2] * SCALE + bias_f(eq1, ek0, alpha);
            S[nt][3] = S[nt][3] * SCALE + bias_f(eq1, ek1, alpha);
            rm0 = fmaxf(rm0, fmaxf(S[nt][0], S[nt][1]));
            rm1 = fmaxf(rm1, fmaxf(S[nt][2], S[nt][3]));
        }
        rm0 = fmaxf(rm0, __shfl_xor_sync(0xffffffffu, rm0, 1));
        rm0 = fmaxf(rm0, __shfl_xor_sync(0xffffffffu, rm0, 2));
        rm1 = fmaxf(rm1, __shfl_xor_sync(0xffffffffu, rm1, 1));
        rm1 = fmaxf(rm1, __shfl_xor_sync(0xffffffffu, rm1, 2));
        float mn0 = fmaxf(mi0, rm0), mn1 = fmaxf(mi1, rm1);
        float c0 = __expf(mi0 - mn0), c1 = __expf(mi1 - mn1);
        mi0 = mn0; mi1 = mn1;
        float rs0 = 0.0f, rs1 = 0.0f;
        #pragma unroll
        for (int nt = 0; nt < 8; nt++) {
            S[nt][0] = __expf(S[nt][0] - mn0); rs0 += S[nt][0];
            S[nt][1] = __expf(S[nt][1] - mn0); rs0 += S[nt][1];
            S[nt][2] = __expf(S[nt][2] - mn1); rs1 += S[nt][2];
            S[nt][3] = __expf(S[nt][3] - mn1); rs1 += S[nt][3];
        }
        rs0 += __shfl_xor_sync(0xffffffffu, rs0, 1);
        rs0 += __shfl_xor_sync(0xffffffffu, rs0, 2);
        rs1 += __shfl_xor_sync(0xffffffffu, rs1, 1);
        rs1 += __shfl_xor_sync(0xffffffffu, rs1, 2);
        li0 = li0 * c0 + rs0;
        li1 = li1 * c1 + rs1;
        #pragma unroll
        for (int e = 0; e < 8; e++) {
            O[e][0] *= c0; O[e][1] *= c0; O[e][2] *= c1; O[e][3] *= c1;
        }

        // P (fp16) into own 16 rows of QP region (warp-private)
        #pragma unroll
        for (int nt = 0; nt < 8; nt++) {
            *(__half2*)&dsm[AOFF_QP + (qr0 + g) * KPWH + nt * 8 + t * 2] =
                __floats2half2_rn(S[nt][0], S[nt][1]);
            *(__half2*)&dsm[AOFF_QP + (qr0 + 8 + g) * KPWH + nt * 8 + t * 2] =
                __floats2half2_rn(S[nt][2], S[nt][3]);
        }
        __syncwarp();

        // O += P @ V
        #pragma unroll
        for (int kc = 0; kc < 4; kc++) {
            uint32_t pf[4];
            ldsm4(pf, aAddr + kc * 32);
            #pragma unroll
            for (int nt4 = 0; nt4 < 4; nt4++) {
                uint32_t bf[4];
                ldsm4(bf, bAddrV[nt4] + bOff + kc * 32);
                mma16(O[nt4 * 2],     pf, bf[0], bf[1]);
                mma16(O[nt4 * 2 + 1], pf, bf[2], bf[3]);
            }
        }
    }

    float inv0 = 1.0f / li0, inv1 = 1.0f / li1;
    int row0 = b * Nseq + q0 + qr0 + g;
    #pragma unroll
    for (int e = 0; e < 8; e++) {
        int col = h * HDim + e * 8 + t * 2;
        *(__half2*)&out[(size_t)row0 * Dm + col] =
            __floats2half2_rn(O[e][0] * inv0, O[e][1] * inv0);
        *(__half2*)&out[(size_t)(row0 + 8) * Dm + col] =
            __floats2half2_rn(O[e][2] * inv1, O[e][3] * inv1);
    }
}

// ---------------- launch ----------------
extern "C" void kernel_launch(void* const* d_in, const int* in_sizes, int n_in,
                              void* d_out, int out_size)
{
    const float* x     = (const float*)d_in[0];
    const float* elev  = (const float*)d_in[1];
    const float* ln1g  = (const float*)d_in[2];
    const float* ln1b  = (const float*)d_in[3];
    const float* qkvw  = (const float*)d_in[4];
    const float* alpha = (const float*)d_in[5];
    const float* projw = (const float*)d_in[6];
    const float* projb = (const float*)d_in[7];
    const float* ln2g  = (const float*)d_in[8];
    const float* ln2b  = (const float*)d_in[9];
    const float* fc1w  = (const float*)d_in[10];
    const float* fc1b  = (const float*)d_in[11];
    const float* fc2w  = (const float*)d_in[12];
    const float* fc2b  = (const float*)d_in[13];
    float* out = (float*)d_out;

    __half *ph, *pqkv, *pattn, *pact, *pwt, *pvt;
    float *px1;
    cudaGetSymbolAddress((void**)&ph,    g_h);
    cudaGetSymbolAddress((void**)&pqkv,  g_qkv);
    cudaGetSymbolAddress((void**)&pattn, g_attn);
    cudaGetSymbolAddress((void**)&px1,   g_x1);
    cudaGetSymbolAddress((void**)&pact,  g_act);
    cudaGetSymbolAddress((void**)&pwt,   g_wt);
    cudaGetSymbolAddress((void**)&pvt,   g_vT);

    cudaFuncSetAttribute(attn_tc,
        cudaFuncAttributeMaxDynamicSharedMemorySize, ATT_BYTES);
    cudaFuncSetAttribute(tgemm<1536, 512, false, false, false, true>,
        cudaFuncAttributeMaxDynamicSharedMemorySize, GSMEM_B);
    cudaFuncSetAttribute(tgemm<512, 512, true, false, true, false>,
        cudaFuncAttributeMaxDynamicSharedMemorySize, GSMEM_B);
    cudaFuncSetAttribute(tgemm<2048, 512, true, true, false, true>,
        cudaFuncAttributeMaxDynamicSharedMemorySize, GSMEM_B);
    cudaFuncSetAttribute(tgemm<512, 2048, true, false, true, false>,
        cudaFuncAttributeMaxDynamicSharedMemorySize, GSMEM_B);

    // 0. all weight transposes (fp32 -> fp16 [n][k]) in one launch
    transpose_all<<<3072, dim3(32, 8)>>>(qkvw, projw, fc1w, fc2w, pwt);

    // 1. LN1 -> fp16
    ln_kernel<<<ROWS, 128>>>(x, ln1g, ln1b, ph);
    // 2. qkv = h @ qkv_w -> fp16
    tgemm<1536, 512, false, false, false, true><<<dim3(12, 64), 128, GSMEM_B>>>(
        ph, pwt + WT_QKV, nullptr, nullptr, pqkv);
    // 3. V transpose (fp16)
    vtrans_kernel<<<dim3(64, 2, 32), dim3(32, 8)>>>(pqkv, pvt);
    // 4. attention -> fp16
    attn_tc<<<dim3(Nseq / 128, Bsz * Hh), 256, ATT_BYTES>>>(
        pqkv, pvt, elev, alpha, pattn);
    // 5. x1 = x + attn @ proj_w + proj_b  (fp32 out)
    tgemm<512, 512, true, false, true, false><<<dim3(4, 64), 128, GSMEM_B>>>(
        pattn, pwt + WT_PROJ, projb, x, px1);
    // 6. LN2 -> fp16
    ln_kernel<<<ROWS, 128>>>(px1, ln2g, ln2b, ph);
    // 7. act = gelu(h2 @ fc1_w + fc1_b) -> fp16
    tgemm<2048, 512, true, true, false, true><<<dim3(16, 64), 128, GSMEM_B>>>(
        ph, pwt + WT_FC1, fc1b, nullptr, pact);
    // 8. out = x1 + act @ fc2_w + fc2_b  (fp32 out)
    tgemm<512, 2048, true, false, true, false><<<dim3(4, 64), 128, GSMEM_B>>>(
        pact, pwt + WT_FC2, fc2b, px1, out);
}

// round 13
// speedup vs baseline: 1.7984x; 1.0288x over previous
#include <cuda_runtime.h>
#include <cuda_fp16.h>
#include <math.h>
#include <stdint.h>

#define Bsz   4
#define Nseq  2048
#define Dm    512
#define Hh    8
#define HDim  64
#define MLPH  2048
#define ROWS  (Bsz * Nseq)
#define SCALE 0.125f

// ---------------- scratch ----------------
__device__ __half g_h[ROWS * Dm];
__device__ __half g_qkv[ROWS * 3 * Dm];
__device__ __half g_attn[ROWS * Dm];
__device__ float  g_x1[ROWS * Dm];
__device__ __half g_act[ROWS * MLPH];
__device__ __half g_wt[3145728];
#define WT_QKV  0
#define WT_PROJ 786432
#define WT_FC1  1048576
#define WT_FC2  2097152

// ---------------- helpers ----------------
__device__ __forceinline__ uint32_t smem_u32(const void* p) {
    return (uint32_t)__cvta_generic_to_shared(p);
}
__device__ __forceinline__ void ldsm4(uint32_t r[4], uint32_t a) {
    asm volatile("ldmatrix.sync.aligned.m8n8.x4.shared.b16 {%0,%1,%2,%3}, [%4];"
        : "=r"(r[0]), "=r"(r[1]), "=r"(r[2]), "=r"(r[3]) : "r"(a));
}
__device__ __forceinline__ void ldsm4t(uint32_t r[4], uint32_t a) {
    asm volatile("ldmatrix.sync.aligned.m8n8.x4.trans.shared.b16 {%0,%1,%2,%3}, [%4];"
        : "=r"(r[0]), "=r"(r[1]), "=r"(r[2]), "=r"(r[3]) : "r"(a));
}
__device__ __forceinline__ void mma16(float d[4], const uint32_t a[4],
                                      uint32_t b0, uint32_t b1) {
    asm volatile(
        "mma.sync.aligned.m16n8k16.row.col.f32.f16.f16.f32 "
        "{%0,%1,%2,%3}, {%4,%5,%6,%7}, {%8,%9}, {%0,%1,%2,%3};"
        : "+f"(d[0]), "+f"(d[1]), "+f"(d[2]), "+f"(d[3])
        : "r"(a[0]), "r"(a[1]), "r"(a[2]), "r"(a[3]), "r"(b0), "r"(b1));
}
__device__ __forceinline__ void cpa16(uint32_t dst, const void* src) {
    asm volatile("cp.async.cg.shared.global [%0], [%1], 16;\n"
        :: "r"(dst), "l"(src));
}
#define CP_COMMIT() asm volatile("cp.async.commit_group;\n" ::: "memory")
#define CP_WAIT1()  asm volatile("cp.async.wait_group 1;\n" ::: "memory")
#define CP_WAIT0()  asm volatile("cp.async.wait_group 0;\n" ::: "memory")

// ---------------- merged weight transpose -> fp16 [n][k] ----------------
__global__ __launch_bounds__(256) void transpose_all(
    const float* __restrict__ qkvw, const float* __restrict__ projw,
    const float* __restrict__ fc1w, const float* __restrict__ fc2w,
    __half* __restrict__ wt)
{
    __shared__ float t[32][33];
    int bid = blockIdx.x;
    const float* in; __half* out; int K, N, rel, nx;
    if (bid < 768)       { in = qkvw;  out = wt + WT_QKV;  K = 512;  N = 1536; rel = bid;        nx = 48; }
    else if (bid < 1024) { in = projw; out = wt + WT_PROJ; K = 512;  N = 512;  rel = bid - 768;  nx = 16; }
    else if (bid < 2048) { in = fc1w;  out = wt + WT_FC1;  K = 512;  N = 2048; rel = bid - 1024; nx = 64; }
    else                 { in = fc2w;  out = wt + WT_FC2;  K = 2048; N = 512;  rel = bid - 2048; nx = 16; }
    int n0 = (rel % nx) * 32, k0 = (rel / nx) * 32;
    int tx = threadIdx.x, ty = threadIdx.y;
    #pragma unroll
    for (int j = 0; j < 32; j += 8)
        t[ty + j][tx] = in[(size_t)(k0 + ty + j) * N + n0 + tx];
    __syncthreads();
    #pragma unroll
    for (int j = 0; j < 32; j += 8)
        out[(size_t)(n0 + ty + j) * K + k0 + tx] = __float2half_rn(t[tx][ty + j]);
}

// ---------------- LayerNorm (fp32 in -> fp16 out) ----------------
__global__ __launch_bounds__(128) void ln_kernel(
    const float* __restrict__ in, const float* __restrict__ gamma,
    const float* __restrict__ beta, __half* __restrict__ out)
{
    int row = blockIdx.x;
    int tid = threadIdx.x;
    const float4* p = (const float4*)(in + (size_t)row * Dm);
    float4 v = p[tid];
    float s  = v.x + v.y + v.z + v.w;
    float ss = v.x * v.x + v.y * v.y + v.z * v.z + v.w * v.w;
    #pragma unroll
    for (int o = 16; o; o >>= 1) {
        s  += __shfl_xor_sync(0xffffffffu, s,  o);
        ss += __shfl_xor_sync(0xffffffffu, ss, o);
    }
    __shared__ float sm[8];
    int w = tid >> 5, lane = tid & 31;
    if (lane == 0) { sm[w] = s; sm[4 + w] = ss; }
    __syncthreads();
    float tot  = sm[0] + sm[1] + sm[2] + sm[3];
    float tot2 = sm[4] + sm[5] + sm[6] + sm[7];
    float mean = tot * (1.0f / Dm);
    float var  = tot2 * (1.0f / Dm) - mean * mean;
    float inv  = rsqrtf(var + 1e-5f);
    float4 g4 = ((const float4*)gamma)[tid];
    float4 b4 = ((const float4*)beta)[tid];
    __half2* op = (__half2*)(out + (size_t)row * Dm);
    op[tid * 2]     = __floats2half2_rn((v.x - mean) * inv * g4.x + b4.x,
                                        (v.y - mean) * inv * g4.y + b4.y);
    op[tid * 2 + 1] = __floats2half2_rn((v.z - mean) * inv * g4.z + b4.z,
                                        (v.w - mean) * inv * g4.w + b4.w);
}

// ---------------- FP16 GEMM (unchanged from R12) ----------------
#define GSTG_B  16384
#define GBOFF   49152
#define GSMEM_B 98304

__device__ __forceinline__ float gelu_exact(float x) {
    return 0.5f * x * (1.0f + erff(x * 0.70710678118654752f));
}

template<int N, int K, bool BIAS, bool GELU, bool RES, bool HOUT>
__global__ __launch_bounds__(128, 2) void tgemm(
    const __half* __restrict__ A, const __half* __restrict__ WT,
    const float* __restrict__ bias, const float* __restrict__ res,
    void* __restrict__ Cv)
{
    extern __shared__ uint32_t gsm[];
    uint32_t smb = smem_u32(gsm);

    int tid = threadIdx.x, lane = tid & 31, warp = tid >> 5;
    int brow = blockIdx.y * 128, bcol = blockIdx.x * 128;
    int wm = (warp >> 1) * 64, wn = (warp & 1) * 64;
    int la = lane & 7, grp = lane >> 3, g = lane >> 2, t = lane & 3;

    int r0 = tid >> 3, kc = tid & 7;
    const __half* Ag = A  + (size_t)(brow + r0) * K + kc * 8;
    const __half* Bg = WT + (size_t)(bcol + r0) * K + kc * 8;
    uint32_t dA = smb + (uint32_t)(r0 * 128 + ((kc ^ (r0 & 7)) << 4));
    uint32_t dB = dA + GBOFF;

    uint32_t aAddr[4];
    #pragma unroll
    for (int mi = 0; mi < 4; mi++) {
        int r = wm + mi * 16 + la + (grp & 1) * 8;
        int c = grp >> 1;
        aAddr[mi] = smb + (uint32_t)(r * 128 + ((c ^ (r & 7)) << 4));
    }
    uint32_t bAddr[4];
    #pragma unroll
    for (int nt = 0; nt < 4; nt++) {
        int n = wn + nt * 16 + (lane & 7) + ((lane >> 4) & 1) * 8;
        int c = (lane >> 3) & 1;
        bAddr[nt] = smb + GBOFF + (uint32_t)(n * 128 + ((c ^ (n & 7)) << 4));
    }

    float acc[4][8][4];
    #pragma unroll
    for (int mi = 0; mi < 4; mi++)
        #pragma unroll
        for (int ni = 0; ni < 8; ni++)
            #pragma unroll
            for (int c = 0; c < 4; c++) acc[mi][ni][c] = 0.0f;

    constexpr int iters = K / 64;

    #pragma unroll
    for (int p = 0; p < 2; p++) {
        uint32_t oa = dA + p * GSTG_B, ob = dB + p * GSTG_B;
        const __half* a = Ag + p * 64;
        const __half* w = Bg + p * 64;
        #pragma unroll
        for (int i = 0; i < 8; i++) {
            cpa16(oa + i * 2048, a + (size_t)i * 16 * K);
            cpa16(ob + i * 2048, w + (size_t)i * 16 * K);
        }
        CP_COMMIT();
    }

    #pragma unroll 1
    for (int it = 0; it < iters; ++it) {
        CP_WAIT1();
        __syncthreads();
        if (it + 2 < iters) {
            uint32_t so = (uint32_t)(((it + 2) % 3) * GSTG_B);
            const __half* a = Ag + (it + 2) * 64;
            const __half* w = Bg + (it + 2) * 64;
            #pragma unroll
            for (int i = 0; i < 8; i++) {
                cpa16(dA + so + i * 2048, a + (size_t)i * 16 * K);
                cpa16(dB + so + i * 2048, w + (size_t)i * 16 * K);
            }
        }
        CP_COMMIT();

        uint32_t so = (uint32_t)((it % 3) * GSTG_B);

        uint32_t af[2][4][4], bf[2][4][4];
        #pragma unroll
        for (int mi = 0; mi < 4; mi++) ldsm4(af[0][mi], aAddr[mi] + so);
        #pragma unroll
        for (int nt = 0; nt < 4; nt++) ldsm4(bf[0][nt], bAddr[nt] + so);

        #pragma unroll
        for (int ks = 0; ks < 4; ks++) {
            int cur = ks & 1, nxt = cur ^ 1;
            if (ks < 3) {
                uint32_t kx = (uint32_t)((ks + 1) << 5);
                #pragma unroll
                for (int mi = 0; mi < 4; mi++)
                    ldsm4(af[nxt][mi], (aAddr[mi] + so) ^ kx);
                #pragma unroll
                for (int nt = 0; nt < 4; nt++)
                    ldsm4(bf[nxt][nt], (bAddr[nt] + so) ^ kx);
            }
            #pragma unroll
            for (int nt = 0; nt < 4; nt++) {
                #pragma unroll
                for (int mi = 0; mi < 4; mi++) {
                    mma16(acc[mi][nt * 2],     af[cur][mi], bf[cur][nt][0], bf[cur][nt][1]);
                    mma16(acc[mi][nt * 2 + 1], af[cur][mi], bf[cur][nt][2], bf[cur][nt][3]);
                }
            }
        }
    }

    #pragma unroll
    for (int mi = 0; mi < 4; mi++) {
        int r0e = brow + wm + mi * 16 + g;
        #pragma unroll
        for (int ni = 0; ni < 8; ni++) {
            int col = bcol + wn + ni * 8 + t * 2;
            float2 v0 = {acc[mi][ni][0], acc[mi][ni][1]};
            float2 v1 = {acc[mi][ni][2], acc[mi][ni][3]};
            if (BIAS) {
                float2 bb = *(const float2*)&bias[col];
                v0.x += bb.x; v0.y += bb.y; v1.x += bb.x; v1.y += bb.y;
            }
            if (GELU) {
                v0.x = gelu_exact(v0.x); v0.y = gelu_exact(v0.y);
                v1.x = gelu_exact(v1.x); v1.y = gelu_exact(v1.y);
            }
            if (RES) {
                float2 q0 = *(const float2*)&res[(size_t)r0e * N + col];
                float2 q1 = *(const float2*)&res[(size_t)(r0e + 8) * N + col];
                v0.x += q0.x; v0.y += q0.y; v1.x += q1.x; v1.y += q1.y;
            }
            if (HOUT) {
                __half* C = (__half*)Cv;
                *(__half2*)&C[(size_t)r0e * N + col]       = __floats2half2_rn(v0.x, v0.y);
                *(__half2*)&C[(size_t)(r0e + 8) * N + col] = __floats2half2_rn(v1.x, v1.y);
            } else {
                float* C = (float*)Cv;
                *(float2*)&C[(size_t)r0e * N + col] = v0;
                *(float2*)&C[(size_t)(r0e + 8) * N + col] = v1;
            }
        }
    }
}

// ---------------- FP16 flash attention: V via ldsm.trans (no vT) ---------
#define KPWH   72
#define AOFF_QP 0
#define AOFF_K  9216
#define AOFF_V  18432
#define AOFF_EK 27648
#define ATT_BYTES 55808
#define KVSTGH  4608

__device__ __forceinline__ float bias_f(float eq, float ek, float alpha) {
    float diff = (ek - eq) * 1e-3f;
    float b = -alpha * fmaxf(diff, 0.0f);
    return fminf(fmaxf(b, -10.0f), 0.0f);
}

__global__ __launch_bounds__(256, 2) void attn_tc(
    const __half* __restrict__ qkv, const float* __restrict__ elev,
    const float* __restrict__ alpha_p, __half* __restrict__ out)
{
    extern __shared__ __half dsm[];
    uint32_t smb = smem_u32(dsm);
    float* sEK = (float*)(dsm + AOFF_EK);

    int bh = blockIdx.y;
    int b = bh >> 3, h = bh & 7;
    int q0 = blockIdx.x * 128;
    int tid = threadIdx.x, lane = tid & 31, warp = tid >> 5;
    int la = lane & 7, grp = lane >> 3, g = lane >> 2, t = lane & 3;
    float alpha = alpha_p[0];
    const float* eb = elev + b * Nseq;
    const __half* qbase = qkv + ((size_t)(b * Nseq + q0)) * (3 * Dm) + h * HDim;
    const __half* kvb   = qkv + ((size_t)(b * Nseq)) * (3 * Dm) + Dm + h * HDim;

    // stage Q + K/V tile 0 (V row-major from qkv: kvb + Dm)
    #pragma unroll
    for (int i = 0; i < 4; i++) {
        int idx = tid + i * 256;
        int r = idx >> 3, c8 = (idx & 7) * 8;
        cpa16(smb + (uint32_t)(AOFF_QP + r * KPWH + c8) * 2u,
              qbase + (size_t)r * (3 * Dm) + c8);
    }
    #pragma unroll
    for (int i = 0; i < 2; i++) {
        int idx = tid + i * 256;
        int r = idx >> 3, c8 = (idx & 7) * 8;
        const __half* src = kvb + (size_t)r * (3 * Dm) + c8;
        cpa16(smb + (uint32_t)(AOFF_K + r * KPWH + c8) * 2u, src);
        cpa16(smb + (uint32_t)(AOFF_V + r * KPWH + c8) * 2u, src + Dm);
    }
    if (tid < 64) sEK[tid] = eb[tid];
    CP_COMMIT();
    CP_WAIT0();
    __syncthreads();

    int qr0 = warp * 16;
    uint32_t aAddr = smb +
        (uint32_t)(AOFF_QP + (qr0 + la + (grp & 1) * 8) * KPWH + (grp >> 1) * 8) * 2u;
    uint32_t qf[4][4];
    #pragma unroll
    for (int kc = 0; kc < 4; kc++) ldsm4(qf[kc], aAddr + kc * 32);

    float eq0 = eb[q0 + qr0 + g];
    float eq1 = eb[q0 + qr0 + g + 8];

    // K fragments (non-trans): rows = keys, consecutive along d
    uint32_t bAddrK[4];
    #pragma unroll
    for (int nt = 0; nt < 4; nt++) {
        int r = nt * 16 + la + (grp >> 1) * 8;
        bAddrK[nt] = smb + (uint32_t)(AOFF_K + r * KPWH + (grp & 1) * 8) * 2u;
    }
    // V fragments (trans): row = kc*16 + (grp&1)*8 + la, chunk = nt*16 + (grp>>1)*8
    uint32_t vBase[4];
    #pragma unroll
    for (int nt = 0; nt < 4; nt++) {
        vBase[nt] = smb + (uint32_t)(AOFF_V + ((grp & 1) * 8 + la) * KPWH
                                     + nt * 16 + (grp >> 1) * 8) * 2u;
    }

    float O[8][4];
    #pragma unroll
    for (int e = 0; e < 8; e++)
        O[e][0] = O[e][1] = O[e][2] = O[e][3] = 0.0f;
    float mi0 = -1e30f, mi1 = -1e30f, li0 = 0.0f, li1 = 0.0f;

    #pragma unroll 1
    for (int tt = 0; tt < Nseq / 64; tt++) {
        if (tt) { CP_WAIT0(); __syncthreads(); }
        if (tt + 1 < Nseq / 64) {
            int bufn = (tt + 1) & 1;
            int k0n = (tt + 1) * 64;
            const __half* kb = kvb + (size_t)k0n * (3 * Dm);
            #pragma unroll
            for (int i = 0; i < 2; i++) {
                int idx = tid + i * 256;
                int r = idx >> 3, c8 = (idx & 7) * 8;
                const __half* src = kb + (size_t)r * (3 * Dm) + c8;
                cpa16(smb + (uint32_t)(AOFF_K + bufn * KVSTGH + r * KPWH + c8) * 2u, src);
                cpa16(smb + (uint32_t)(AOFF_V + bufn * KVSTGH + r * KPWH + c8) * 2u, src + Dm);
            }
            if (tid < 64) sEK[bufn * 64 + tid] = eb[k0n + tid];
        }
        CP_COMMIT();

        int buf = tt & 1;
        uint32_t bOff = (uint32_t)(buf * KVSTGH) * 2u;

        // S = Q K^T
        float S[8][4];
        #pragma unroll
        for (int nt = 0; nt < 8; nt++)
            S[nt][0] = S[nt][1] = S[nt][2] = S[nt][3] = 0.0f;
        #pragma unroll
        for (int kc = 0; kc < 4; kc++) {
            #pragma unroll
            for (int nt4 = 0; nt4 < 4; nt4++) {
                uint32_t bf[4];
                ldsm4(bf, bAddrK[nt4] + bOff + kc * 32);
                mma16(S[nt4 * 2],     qf[kc], bf[0], bf[1]);
                mma16(S[nt4 * 2 + 1], qf[kc], bf[2], bf[3]);
            }
        }

        float rm0 = -1e30f, rm1 = -1e30f;
        #pragma unroll
        for (int nt = 0; nt < 8; nt++) {
            float ek0 = sEK[buf * 64 + nt * 8 + t * 2];
            float ek1 = sEK[buf * 64 + nt * 8 + t * 2 + 1];
            S[nt][0] = S[nt][0] * SCALE + bias_f(eq0, ek0, alpha);
            S[nt][1] = S[nt][1] * SCALE + bias_f(eq0, ek1, alpha);
            S[nt][2] = S[nt][2] * SCALE + bias_f(eq1, ek0, alpha);
            S[nt][3] = S[nt][3] * SCALE + bias_f(eq1, ek1, alpha);
            rm0 = fmaxf(rm0, fmaxf(S[nt][0], S[nt][1]));
            rm1 = fmaxf(rm1, fmaxf(S[nt][2], S[nt][3]));
        }
        rm0 = fmaxf(rm0, __shfl_xor_sync(0xffffffffu, rm0, 1));
        rm0 = fmaxf(rm0, __shfl_xor_sync(0xffffffffu, rm0, 2));
        rm1 = fmaxf(rm1, __shfl_xor_sync(0xffffffffu, rm1, 1));
        rm1 = fmaxf(rm1, __shfl_xor_sync(0xffffffffu, rm1, 2));
        float mn0 = fmaxf(mi0, rm0), mn1 = fmaxf(mi1, rm1);
        float c0 = __expf(mi0 - mn0), c1 = __expf(mi1 - mn1);
        mi0 = mn0; mi1 = mn1;
        float rs0 = 0.0f, rs1 = 0.0f;
        #pragma unroll
        for (int nt = 0; nt < 8; nt++) {
            S[nt][0] = __expf(S[nt][0] - mn0); rs0 += S[nt][0];
            S[nt][1] = __expf(S[nt][1] - mn0); rs0 += S[nt][1];
            S[nt][2] = __expf(S[nt][2] - mn1); rs1 += S[nt][2];
            S[nt][3] = __expf(S[nt][3] - mn1); rs1 += S[nt][3];
        }
        rs0 += __shfl_xor_sync(0xffffffffu, rs0, 1);
        rs0 += __shfl_xor_sync(0xffffffffu, rs0, 2);
        rs1 += __shfl_xor_sync(0xffffffffu, rs1, 1);
        rs1 += __shfl_xor_sync(0xffffffffu, rs1, 2);
        li0 = li0 * c0 + rs0;
        li1 = li1 * c1 + rs1;
        #pragma unroll
        for (int e = 0; e < 8; e++) {
            O[e][0] *= c0; O[e][1] *= c0; O[e][2] *= c1; O[e][3] *= c1;
        }

        // P (fp16) into own 16 rows of QP region
        #pragma unroll
        for (int nt = 0; nt < 8; nt++) {
            *(__half2*)&dsm[AOFF_QP + (qr0 + g) * KPWH + nt * 8 + t * 2] =
                __floats2half2_rn(S[nt][0], S[nt][1]);
            *(__half2*)&dsm[AOFF_QP + (qr0 + 8 + g) * KPWH + nt * 8 + t * 2] =
                __floats2half2_rn(S[nt][2], S[nt][3]);
        }
        __syncwarp();

        // O += P @ V  (V fragments via ldsm.trans on row-major V)
        #pragma unroll
        for (int kc = 0; kc < 4; kc++) {
            uint32_t pf[4];
            ldsm4(pf, aAddr + kc * 32);
            uint32_t kRow = bOff + (uint32_t)(kc * 16 * KPWH) * 2u;
            #pragma unroll
            for (int nt4 = 0; nt4 < 4; nt4++) {
                uint32_t bf[4];
                ldsm4t(bf, vBase[nt4] + kRow);
                mma16(O[nt4 * 2],     pf, bf[0], bf[1]);
                mma16(O[nt4 * 2 + 1], pf, bf[2], bf[3]);
            }
        }
    }

    float inv0 = 1.0f / li0, inv1 = 1.0f / li1;
    int row0 = b * Nseq + q0 + qr0 + g;
    #pragma unroll
    for (int e = 0; e < 8; e++) {
        int col = h * HDim + e * 8 + t * 2;
        *(__half2*)&out[(size_t)row0 * Dm + col] =
            __floats2half2_rn(O[e][0] * inv0, O[e][1] * inv0);
        *(__half2*)&out[(size_t)(row0 + 8) * Dm + col] =
            __floats2half2_rn(O[e][2] * inv1, O[e][3] * inv1);
    }
}

// ---------------- launch ----------------
extern "C" void kernel_launch(void* const* d_in, const int* in_sizes, int n_in,
                              void* d_out, int out_size)
{
    const float* x     = (const float*)d_in[0];
    const float* elev  = (const float*)d_in[1];
    const float* ln1g  = (const float*)d_in[2];
    const float* ln1b  = (const float*)d_in[3];
    const float* qkvw  = (const float*)d_in[4];
    const float* alpha = (const float*)d_in[5];
    const float* projw = (const float*)d_in[6];
    const float* projb = (const float*)d_in[7];
    const float* ln2g  = (const float*)d_in[8];
    const float* ln2b  = (const float*)d_in[9];
    const float* fc1w  = (const float*)d_in[10];
    const float* fc1b  = (const float*)d_in[11];
    const float* fc2w  = (const float*)d_in[12];
    const float* fc2b  = (const float*)d_in[13];
    float* out = (float*)d_out;

    __half *ph, *pqkv, *pattn, *pact, *pwt;
    float *px1;
    cudaGetSymbolAddress((void**)&ph,    g_h);
    cudaGetSymbolAddress((void**)&pqkv,  g_qkv);
    cudaGetSymbolAddress((void**)&pattn, g_attn);
    cudaGetSymbolAddress((void**)&px1,   g_x1);
    cudaGetSymbolAddress((void**)&pact,  g_act);
    cudaGetSymbolAddress((void**)&pwt,   g_wt);

    cudaFuncSetAttribute(attn_tc,
        cudaFuncAttributeMaxDynamicSharedMemorySize, ATT_BYTES);
    cudaFuncSetAttribute(tgemm<1536, 512, false, false, false, true>,
        cudaFuncAttributeMaxDynamicSharedMemorySize, GSMEM_B);
    cudaFuncSetAttribute(tgemm<512, 512, true, false, true, false>,
        cudaFuncAttributeMaxDynamicSharedMemorySize, GSMEM_B);
    cudaFuncSetAttribute(tgemm<2048, 512, true, true, false, true>,
        cudaFuncAttributeMaxDynamicSharedMemorySize, GSMEM_B);
    cudaFuncSetAttribute(tgemm<512, 2048, true, false, true, false>,
        cudaFuncAttributeMaxDynamicSharedMemorySize, GSMEM_B);

    // 0. all weight transposes (fp32 -> fp16 [n][k]) in one launch
    transpose_all<<<3072, dim3(32, 8)>>>(qkvw, projw, fc1w, fc2w, pwt);

    // 1. LN1 -> fp16
    ln_kernel<<<ROWS, 128>>>(x, ln1g, ln1b, ph);
    // 2. qkv = h @ qkv_w -> fp16
    tgemm<1536, 512, false, false, false, true><<<dim3(12, 64), 128, GSMEM_B>>>(
        ph, pwt + WT_QKV, nullptr, nullptr, pqkv);
    // 3. attention -> fp16 (V loaded directly; no transpose stage)
    attn_tc<<<dim3(Nseq / 128, Bsz * Hh), 256, ATT_BYTES>>>(
        pqkv, elev, alpha, pattn);
    // 4. x1 = x + attn @ proj_w + proj_b  (fp32 out)
    tgemm<512, 512, true, false, true, false><<<dim3(4, 64), 128, GSMEM_B>>>(
        pattn, pwt + WT_PROJ, projb, x, px1);
    // 5. LN2 -> fp16
    ln_kernel<<<ROWS, 128>>>(px1, ln2g, ln2b, ph);
    // 6. act = gelu(h2 @ fc1_w + fc1_b) -> fp16
    tgemm<2048, 512, true, true, false, true><<<dim3(16, 64), 128, GSMEM_B>>>(
        ph, pwt + WT_FC1, fc1b, nullptr, pact);
    // 7. out = x1 + act @ fc2_w + fc2_b  (fp32 out)
    tgemm<512, 2048, true, false, true, false><<<dim3(4, 64), 128, GSMEM_B>>>(
        pact, pwt + WT_FC2, fc2b, px1, out);
}

// round 14
// speedup vs baseline: 1.8619x; 1.0353x over previous
#include <cuda_runtime.h>
#include <cuda_fp16.h>
#include <math.h>
#include <stdint.h>

#define Bsz   4
#define Nseq  2048
#define Dm    512
#define Hh    8
#define HDim  64
#define MLPH  2048
#define ROWS  (Bsz * Nseq)
#define SCALE 0.125f
#define LOG2E 1.4426950408889634f

// ---------------- scratch ----------------
__device__ __half g_h[ROWS * Dm];
__device__ __half g_qkv[ROWS * 3 * Dm];
__device__ __half g_attn[ROWS * Dm];
__device__ float  g_x1[ROWS * Dm];
__device__ __half g_act[ROWS * MLPH];
__device__ __half g_wt[3145728];
#define WT_QKV  0
#define WT_PROJ 786432
#define WT_FC1  1048576
#define WT_FC2  2097152

// ---------------- helpers ----------------
__device__ __forceinline__ uint32_t smem_u32(const void* p) {
    return (uint32_t)__cvta_generic_to_shared(p);
}
__device__ __forceinline__ float ex2(float x) {
    float r; asm("ex2.approx.f32 %0, %1;" : "=f"(r) : "f"(x)); return r;
}
__device__ __forceinline__ void ldsm4(uint32_t r[4], uint32_t a) {
    asm volatile("ldmatrix.sync.aligned.m8n8.x4.shared.b16 {%0,%1,%2,%3}, [%4];"
        : "=r"(r[0]), "=r"(r[1]), "=r"(r[2]), "=r"(r[3]) : "r"(a));
}
__device__ __forceinline__ void ldsm4t(uint32_t r[4], uint32_t a) {
    asm volatile("ldmatrix.sync.aligned.m8n8.x4.trans.shared.b16 {%0,%1,%2,%3}, [%4];"
        : "=r"(r[0]), "=r"(r[1]), "=r"(r[2]), "=r"(r[3]) : "r"(a));
}
__device__ __forceinline__ void mma16(float d[4], const uint32_t a[4],
                                      uint32_t b0, uint32_t b1) {
    asm volatile(
        "mma.sync.aligned.m16n8k16.row.col.f32.f16.f16.f32 "
        "{%0,%1,%2,%3}, {%4,%5,%6,%7}, {%8,%9}, {%0,%1,%2,%3};"
        : "+f"(d[0]), "+f"(d[1]), "+f"(d[2]), "+f"(d[3])
        : "r"(a[0]), "r"(a[1]), "r"(a[2]), "r"(a[3]), "r"(b0), "r"(b1));
}
__device__ __forceinline__ void cpa16(uint32_t dst, const void* src) {
    asm volatile("cp.async.cg.shared.global [%0], [%1], 16;\n"
        :: "r"(dst), "l"(src));
}
#define CP_COMMIT() asm volatile("cp.async.commit_group;\n" ::: "memory")
#define CP_WAIT1()  asm volatile("cp.async.wait_group 1;\n" ::: "memory")
#define CP_WAIT0()  asm volatile("cp.async.wait_group 0;\n" ::: "memory")

// ---------------- merged weight transpose -> fp16 [n][k] ----------------
__global__ __launch_bounds__(256) void transpose_all(
    const float* __restrict__ qkvw, const float* __restrict__ projw,
    const float* __restrict__ fc1w, const float* __restrict__ fc2w,
    __half* __restrict__ wt)
{
    __shared__ float t[32][33];
    int bid = blockIdx.x;
    const float* in; __half* out; int K, N, rel, nx;
    if (bid < 768)       { in = qkvw;  out = wt + WT_QKV;  K = 512;  N = 1536; rel = bid;        nx = 48; }
    else if (bid < 1024) { in = projw; out = wt + WT_PROJ; K = 512;  N = 512;  rel = bid - 768;  nx = 16; }
    else if (bid < 2048) { in = fc1w;  out = wt + WT_FC1;  K = 512;  N = 2048; rel = bid - 1024; nx = 64; }
    else                 { in = fc2w;  out = wt + WT_FC2;  K = 2048; N = 512;  rel = bid - 2048; nx = 16; }
    int n0 = (rel % nx) * 32, k0 = (rel / nx) * 32;
    int tx = threadIdx.x, ty = threadIdx.y;
    #pragma unroll
    for (int j = 0; j < 32; j += 8)
        t[ty + j][tx] = in[(size_t)(k0 + ty + j) * N + n0 + tx];
    __syncthreads();
    #pragma unroll
    for (int j = 0; j < 32; j += 8)
        out[(size_t)(n0 + ty + j) * K + k0 + tx] = __float2half_rn(t[tx][ty + j]);
}

// ---------------- LayerNorm (fp32 in -> fp16 out) ----------------
__global__ __launch_bounds__(128) void ln_kernel(
    const float* __restrict__ in, const float* __restrict__ gamma,
    const float* __restrict__ beta, __half* __restrict__ out)
{
    int row = blockIdx.x;
    int tid = threadIdx.x;
    const float4* p = (const float4*)(in + (size_t)row * Dm);
    float4 v = p[tid];
    float s  = v.x + v.y + v.z + v.w;
    float ss = v.x * v.x + v.y * v.y + v.z * v.z + v.w * v.w;
    #pragma unroll
    for (int o = 16; o; o >>= 1) {
        s  += __shfl_xor_sync(0xffffffffu, s,  o);
        ss += __shfl_xor_sync(0xffffffffu, ss, o);
    }
    __shared__ float sm[8];
    int w = tid >> 5, lane = tid & 31;
    if (lane == 0) { sm[w] = s; sm[4 + w] = ss; }
    __syncthreads();
    float tot  = sm[0] + sm[1] + sm[2] + sm[3];
    float tot2 = sm[4] + sm[5] + sm[6] + sm[7];
    float mean = tot * (1.0f / Dm);
    float var  = tot2 * (1.0f / Dm) - mean * mean;
    float inv  = rsqrtf(var + 1e-5f);
    float4 g4 = ((const float4*)gamma)[tid];
    float4 b4 = ((const float4*)beta)[tid];
    __half2* op = (__half2*)(out + (size_t)row * Dm);
    op[tid * 2]     = __floats2half2_rn((v.x - mean) * inv * g4.x + b4.x,
                                        (v.y - mean) * inv * g4.y + b4.y);
    op[tid * 2 + 1] = __floats2half2_rn((v.z - mean) * inv * g4.z + b4.z,
                                        (v.w - mean) * inv * g4.w + b4.w);
}

// ---------------- FP16 GEMM (unchanged from R13) ----------------
#define GSTG_B  16384
#define GBOFF   49152
#define GSMEM_B 98304

__device__ __forceinline__ float gelu_exact(float x) {
    return 0.5f * x * (1.0f + erff(x * 0.70710678118654752f));
}

template<int N, int K, bool BIAS, bool GELU, bool RES, bool HOUT>
__global__ __launch_bounds__(128, 2) void tgemm(
    const __half* __restrict__ A, const __half* __restrict__ WT,
    const float* __restrict__ bias, const float* __restrict__ res,
    void* __restrict__ Cv)
{
    extern __shared__ uint32_t gsm[];
    uint32_t smb = smem_u32(gsm);

    int tid = threadIdx.x, lane = tid & 31, warp = tid >> 5;
    int brow = blockIdx.y * 128, bcol = blockIdx.x * 128;
    int wm = (warp >> 1) * 64, wn = (warp & 1) * 64;
    int la = lane & 7, grp = lane >> 3, g = lane >> 2, t = lane & 3;

    int r0 = tid >> 3, kc = tid & 7;
    const __half* Ag = A  + (size_t)(brow + r0) * K + kc * 8;
    const __half* Bg = WT + (size_t)(bcol + r0) * K + kc * 8;
    uint32_t dA = smb + (uint32_t)(r0 * 128 + ((kc ^ (r0 & 7)) << 4));
    uint32_t dB = dA + GBOFF;

    uint32_t aAddr[4];
    #pragma unroll
    for (int mi = 0; mi < 4; mi++) {
        int r = wm + mi * 16 + la + (grp & 1) * 8;
        int c = grp >> 1;
        aAddr[mi] = smb + (uint32_t)(r * 128 + ((c ^ (r & 7)) << 4));
    }
    uint32_t bAddr[4];
    #pragma unroll
    for (int nt = 0; nt < 4; nt++) {
        int n = wn + nt * 16 + (lane & 7) + ((lane >> 4) & 1) * 8;
        int c = (lane >> 3) & 1;
        bAddr[nt] = smb + GBOFF + (uint32_t)(n * 128 + ((c ^ (n & 7)) << 4));
    }

    float acc[4][8][4];
    #pragma unroll
    for (int mi = 0; mi < 4; mi++)
        #pragma unroll
        for (int ni = 0; ni < 8; ni++)
            #pragma unroll
            for (int c = 0; c < 4; c++) acc[mi][ni][c] = 0.0f;

    constexpr int iters = K / 64;

    #pragma unroll
    for (int p = 0; p < 2; p++) {
        uint32_t oa = dA + p * GSTG_B, ob = dB + p * GSTG_B;
        const __half* a = Ag + p * 64;
        const __half* w = Bg + p * 64;
        #pragma unroll
        for (int i = 0; i < 8; i++) {
            cpa16(oa + i * 2048, a + (size_t)i * 16 * K);
            cpa16(ob + i * 2048, w + (size_t)i * 16 * K);
        }
        CP_COMMIT();
    }

    #pragma unroll 1
    for (int it = 0; it < iters; ++it) {
        CP_WAIT1();
        __syncthreads();
        if (it + 2 < iters) {
            uint32_t so = (uint32_t)(((it + 2) % 3) * GSTG_B);
            const __half* a = Ag + (it + 2) * 64;
            const __half* w = Bg + (it + 2) * 64;
            #pragma unroll
            for (int i = 0; i < 8; i++) {
                cpa16(dA + so + i * 2048, a + (size_t)i * 16 * K);
                cpa16(dB + so + i * 2048, w + (size_t)i * 16 * K);
            }
        }
        CP_COMMIT();

        uint32_t so = (uint32_t)((it % 3) * GSTG_B);

        uint32_t af[2][4][4], bf[2][4][4];
        #pragma unroll
        for (int mi = 0; mi < 4; mi++) ldsm4(af[0][mi], aAddr[mi] + so);
        #pragma unroll
        for (int nt = 0; nt < 4; nt++) ldsm4(bf[0][nt], bAddr[nt] + so);

        #pragma unroll
        for (int ks = 0; ks < 4; ks++) {
            int cur = ks & 1, nxt = cur ^ 1;
            if (ks < 3) {
                uint32_t kx = (uint32_t)((ks + 1) << 5);
                #pragma unroll
                for (int mi = 0; mi < 4; mi++)
                    ldsm4(af[nxt][mi], (aAddr[mi] + so) ^ kx);
                #pragma unroll
                for (int nt = 0; nt < 4; nt++)
                    ldsm4(bf[nxt][nt], (bAddr[nt] + so) ^ kx);
            }
            #pragma unroll
            for (int nt = 0; nt < 4; nt++) {
                #pragma unroll
                for (int mi = 0; mi < 4; mi++) {
                    mma16(acc[mi][nt * 2],     af[cur][mi], bf[cur][nt][0], bf[cur][nt][1]);
                    mma16(acc[mi][nt * 2 + 1], af[cur][mi], bf[cur][nt][2], bf[cur][nt][3]);
                }
            }
        }
    }

    #pragma unroll
    for (int mi = 0; mi < 4; mi++) {
        int r0e = brow + wm + mi * 16 + g;
        #pragma unroll
        for (int ni = 0; ni < 8; ni++) {
            int col = bcol + wn + ni * 8 + t * 2;
            float2 v0 = {acc[mi][ni][0], acc[mi][ni][1]};
            float2 v1 = {acc[mi][ni][2], acc[mi][ni][3]};
            if (BIAS) {
                float2 bb = *(const float2*)&bias[col];
                v0.x += bb.x; v0.y += bb.y; v1.x += bb.x; v1.y += bb.y;
            }
            if (GELU) {
                v0.x = gelu_exact(v0.x); v0.y = gelu_exact(v0.y);
                v1.x = gelu_exact(v1.x); v1.y = gelu_exact(v1.y);
            }
            if (RES) {
                float2 q0 = *(const float2*)&res[(size_t)r0e * N + col];
                float2 q1 = *(const float2*)&res[(size_t)(r0e + 8) * N + col];
                v0.x += q0.x; v0.y += q0.y; v1.x += q1.x; v1.y += q1.y;
            }
            if (HOUT) {
                __half* C = (__half*)Cv;
                *(__half2*)&C[(size_t)r0e * N + col]       = __floats2half2_rn(v0.x, v0.y);
                *(__half2*)&C[(size_t)(r0e + 8) * N + col] = __floats2half2_rn(v1.x, v1.y);
            } else {
                float* C = (float*)Cv;
                *(float2*)&C[(size_t)r0e * N + col] = v0;
                *(float2*)&C[(size_t)(r0e + 8) * N + col] = v1;
            }
        }
    }
}

// ---------------- FP16 flash attention, base-2 softmax ----------------
#define KPWH   72
#define AOFF_QP 0
#define AOFF_K  9216
#define AOFF_V  18432
#define AOFF_EK 27648
#define ATT_BYTES 55808
#define KVSTGH  4608

__global__ __launch_bounds__(256, 2) void attn_tc(
    const __half* __restrict__ qkv, const float* __restrict__ elev,
    const float* __restrict__ alpha_p, __half* __restrict__ out)
{
    extern __shared__ __half dsm[];
    uint32_t smb = smem_u32(dsm);
    float* sEK = (float*)(dsm + AOFF_EK);

    int bh = blockIdx.y;
    int b = bh >> 3, h = bh & 7;
    int q0 = blockIdx.x * 128;
    int tid = threadIdx.x, lane = tid & 31, warp = tid >> 5;
    int la = lane & 7, grp = lane >> 3, g = lane >> 2, t = lane & 3;
    const float SCALE2 = SCALE * LOG2E;
    const float LO = -10.0f * LOG2E;
    float negc2 = -alpha_p[0] * (1e-3f * LOG2E);
    const float* eb = elev + b * Nseq;
    const __half* qbase = qkv + ((size_t)(b * Nseq + q0)) * (3 * Dm) + h * HDim;
    const __half* kvb   = qkv + ((size_t)(b * Nseq)) * (3 * Dm) + Dm + h * HDim;

    #pragma unroll
    for (int i = 0; i < 4; i++) {
        int idx = tid + i * 256;
        int r = idx >> 3, c8 = (idx & 7) * 8;
        cpa16(smb + (uint32_t)(AOFF_QP + r * KPWH + c8) * 2u,
              qbase + (size_t)r * (3 * Dm) + c8);
    }
    #pragma unroll
    for (int i = 0; i < 2; i++) {
        int idx = tid + i * 256;
        int r = idx >> 3, c8 = (idx & 7) * 8;
        const __half* src = kvb + (size_t)r * (3 * Dm) + c8;
        cpa16(smb + (uint32_t)(AOFF_K + r * KPWH + c8) * 2u, src);
        cpa16(smb + (uint32_t)(AOFF_V + r * KPWH + c8) * 2u, src + Dm);
    }
    if (tid < 64) sEK[tid] = eb[tid];
    CP_COMMIT();
    CP_WAIT0();
    __syncthreads();

    int qr0 = warp * 16;
    uint32_t aAddr = smb +
        (uint32_t)(AOFF_QP + (qr0 + la + (grp & 1) * 8) * KPWH + (grp >> 1) * 8) * 2u;
    uint32_t qf[4][4];
    #pragma unroll
    for (int kc = 0; kc < 4; kc++) ldsm4(qf[kc], aAddr + kc * 32);

    float eq0 = eb[q0 + qr0 + g];
    float eq1 = eb[q0 + qr0 + g + 8];

    uint32_t bAddrK[4];
    #pragma unroll
    for (int nt = 0; nt < 4; nt++) {
        int r = nt * 16 + la + (grp >> 1) * 8;
        bAddrK[nt] = smb + (uint32_t)(AOFF_K + r * KPWH + (grp & 1) * 8) * 2u;
    }
    uint32_t vBase[4];
    #pragma unroll
    for (int nt = 0; nt < 4; nt++) {
        vBase[nt] = smb + (uint32_t)(AOFF_V + ((grp & 1) * 8 + la) * KPWH
                                     + nt * 16 + (grp >> 1) * 8) * 2u;
    }

    float O[8][4];
    #pragma unroll
    for (int e = 0; e < 8; e++)
        O[e][0] = O[e][1] = O[e][2] = O[e][3] = 0.0f;
    float mi0 = -1e30f, mi1 = -1e30f, li0 = 0.0f, li1 = 0.0f;

    #pragma unroll 1
    for (int tt = 0; tt < Nseq / 64; tt++) {
        if (tt) { CP_WAIT0(); __syncthreads(); }
        if (tt + 1 < Nseq / 64) {
            int bufn = (tt + 1) & 1;
            int k0n = (tt + 1) * 64;
            const __half* kb = kvb + (size_t)k0n * (3 * Dm);
            #pragma unroll
            for (int i = 0; i < 2; i++) {
                int idx = tid + i * 256;
                int r = idx >> 3, c8 = (idx & 7) * 8;
                const __half* src = kb + (size_t)r * (3 * Dm) + c8;
                cpa16(smb + (uint32_t)(AOFF_K + bufn * KVSTGH + r * KPWH + c8) * 2u, src);
                cpa16(smb + (uint32_t)(AOFF_V + bufn * KVSTGH + r * KPWH + c8) * 2u, src + Dm);
            }
            if (tid < 64) sEK[bufn * 64 + tid] = eb[k0n + tid];
        }
        CP_COMMIT();

        int buf = tt & 1;
        uint32_t bOff = (uint32_t)(buf * KVSTGH) * 2u;

        // S = Q K^T
        float S[8][4];
        #pragma unroll
        for (int nt = 0; nt < 8; nt++)
            S[nt][0] = S[nt][1] = S[nt][2] = S[nt][3] = 0.0f;
        #pragma unroll
        for (int kc = 0; kc < 4; kc++) {
            #pragma unroll
            for (int nt4 = 0; nt4 < 4; nt4++) {
                uint32_t bf[4];
                ldsm4(bf, bAddrK[nt4] + bOff + kc * 32);
                mma16(S[nt4 * 2],     qf[kc], bf[0], bf[1]);
                mma16(S[nt4 * 2 + 1], qf[kc], bf[2], bf[3]);
            }
        }

        // base-2 softmax: S2 = S*SCALE2 + bias2 ; p = ex2(S2 - m)
        float rm0 = -1e30f, rm1 = -1e30f;
        #pragma unroll
        for (int nt = 0; nt < 8; nt++) {
            float2 ek = *(const float2*)&sEK[buf * 64 + nt * 8 + t * 2];
            float b00 = fmaxf(negc2 * fmaxf(ek.x - eq0, 0.0f), LO);
            float b01 = fmaxf(negc2 * fmaxf(ek.y - eq0, 0.0f), LO);
            float b10 = fmaxf(negc2 * fmaxf(ek.x - eq1, 0.0f), LO);
            float b11 = fmaxf(negc2 * fmaxf(ek.y - eq1, 0.0f), LO);
            S[nt][0] = fmaf(S[nt][0], SCALE2, b00);
            S[nt][1] = fmaf(S[nt][1], SCALE2, b01);
            S[nt][2] = fmaf(S[nt][2], SCALE2, b10);
            S[nt][3] = fmaf(S[nt][3], SCALE2, b11);
            rm0 = fmaxf(rm0, fmaxf(S[nt][0], S[nt][1]));
            rm1 = fmaxf(rm1, fmaxf(S[nt][2], S[nt][3]));
        }
        rm0 = fmaxf(rm0, __shfl_xor_sync(0xffffffffu, rm0, 1));
        rm0 = fmaxf(rm0, __shfl_xor_sync(0xffffffffu, rm0, 2));
        rm1 = fmaxf(rm1, __shfl_xor_sync(0xffffffffu, rm1, 1));
        rm1 = fmaxf(rm1, __shfl_xor_sync(0xffffffffu, rm1, 2));
        float mn0 = fmaxf(mi0, rm0), mn1 = fmaxf(mi1, rm1);
        float c0 = ex2(mi0 - mn0), c1 = ex2(mi1 - mn1);
        mi0 = mn0; mi1 = mn1;
        float rs0 = 0.0f, rs1 = 0.0f;
        #pragma unroll
        for (int nt = 0; nt < 8; nt++) {
            S[nt][0] = ex2(S[nt][0] - mn0); rs0 += S[nt][0];
            S[nt][1] = ex2(S[nt][1] - mn0); rs0 += S[nt][1];
            S[nt][2] = ex2(S[nt][2] - mn1); rs1 += S[nt][2];
            S[nt][3] = ex2(S[nt][3] - mn1); rs1 += S[nt][3];
        }
        rs0 += __shfl_xor_sync(0xffffffffu, rs0, 1);
        rs0 += __shfl_xor_sync(0xffffffffu, rs0, 2);
        rs1 += __shfl_xor_sync(0xffffffffu, rs1, 1);
        rs1 += __shfl_xor_sync(0xffffffffu, rs1, 2);
        li0 = li0 * c0 + rs0;
        li1 = li1 * c1 + rs1;
        #pragma unroll
        for (int e = 0; e < 8; e++) {
            O[e][0] *= c0; O[e][1] *= c0; O[e][2] *= c1; O[e][3] *= c1;
        }

        // P (fp16) into own 16 rows of QP region
        #pragma unroll
        for (int nt = 0; nt < 8; nt++) {
            *(__half2*)&dsm[AOFF_QP + (qr0 + g) * KPWH + nt * 8 + t * 2] =
                __floats2half2_rn(S[nt][0], S[nt][1]);
            *(__half2*)&dsm[AOFF_QP + (qr0 + 8 + g) * KPWH + nt * 8 + t * 2] =
                __floats2half2_rn(S[nt][2], S[nt][3]);
        }
        __syncwarp();

        // O += P @ V  (V fragments via ldsm.trans on row-major V)
        #pragma unroll
        for (int kc = 0; kc < 4; kc++) {
            uint32_t pf[4];
            ldsm4(pf, aAddr + kc * 32);
            uint32_t kRow = bOff + (uint32_t)(kc * 16 * KPWH) * 2u;
            #pragma unroll
            for (int nt4 = 0; nt4 < 4; nt4++) {
                uint32_t bf[4];
                ldsm4t(bf, vBase[nt4] + kRow);
                mma16(O[nt4 * 2],     pf, bf[0], bf[1]);
                mma16(O[nt4 * 2 + 1], pf, bf[2], bf[3]);
            }
        }
    }

    float inv0 = 1.0f / li0, inv1 = 1.0f / li1;
    int row0 = b * Nseq + q0 + qr0 + g;
    #pragma unroll
    for (int e = 0; e < 8; e++) {
        int col = h * HDim + e * 8 + t * 2;
        *(__half2*)&out[(size_t)row0 * Dm + col] =
            __floats2half2_rn(O[e][0] * inv0, O[e][1] * inv0);
        *(__half2*)&out[(size_t)(row0 + 8) * Dm + col] =
            __floats2half2_rn(O[e][2] * inv1, O[e][3] * inv1);
    }
}

// ---------------- launch ----------------
extern "C" void kernel_launch(void* const* d_in, const int* in_sizes, int n_in,
                              void* d_out, int out_size)
{
    const float* x     = (const float*)d_in[0];
    const float* elev  = (const float*)d_in[1];
    const float* ln1g  = (const float*)d_in[2];
    const float* ln1b  = (const float*)d_in[3];
    const float* qkvw  = (const float*)d_in[4];
    const float* alpha = (const float*)d_in[5];
    const float* projw = (const float*)d_in[6];
    const float* projb = (const float*)d_in[7];
    const float* ln2g  = (const float*)d_in[8];
    const float* ln2b  = (const float*)d_in[9];
    const float* fc1w  = (const float*)d_in[10];
    const float* fc1b  = (const float*)d_in[11];
    const float* fc2w  = (const float*)d_in[12];
    const float* fc2b  = (const float*)d_in[13];
    float* out = (float*)d_out;

    __half *ph, *pqkv, *pattn, *pact, *pwt;
    float *px1;
    cudaGetSymbolAddress((void**)&ph,    g_h);
    cudaGetSymbolAddress((void**)&pqkv,  g_qkv);
    cudaGetSymbolAddress((void**)&pattn, g_attn);
    cudaGetSymbolAddress((void**)&px1,   g_x1);
    cudaGetSymbolAddress((void**)&pact,  g_act);
    cudaGetSymbolAddress((void**)&pwt,   g_wt);

    cudaFuncSetAttribute(attn_tc,
        cudaFuncAttributeMaxDynamicSharedMemorySize, ATT_BYTES);
    cudaFuncSetAttribute(tgemm<1536, 512, false, false, false, true>,
        cudaFuncAttributeMaxDynamicSharedMemorySize, GSMEM_B);
    cudaFuncSetAttribute(tgemm<512, 512, true, false, true, false>,
        cudaFuncAttributeMaxDynamicSharedMemorySize, GSMEM_B);
    cudaFuncSetAttribute(tgemm<2048, 512, true, true, false, true>,
        cudaFuncAttributeMaxDynamicSharedMemorySize, GSMEM_B);
    cudaFuncSetAttribute(tgemm<512, 2048, true, false, true, false>,
        cudaFuncAttributeMaxDynamicSharedMemorySize, GSMEM_B);

    // 0. all weight transposes (fp32 -> fp16 [n][k]) in one launch
    transpose_all<<<3072, dim3(32, 8)>>>(qkvw, projw, fc1w, fc2w, pwt);

    // 1. LN1 -> fp16
    ln_kernel<<<ROWS, 128>>>(x, ln1g, ln1b, ph);
    // 2. qkv = h @ qkv_w -> fp16
    tgemm<1536, 512, false, false, false, true><<<dim3(12, 64), 128, GSMEM_B>>>(
        ph, pwt + WT_QKV, nullptr, nullptr, pqkv);
    // 3. attention -> fp16
    attn_tc<<<dim3(Nseq / 128, Bsz * Hh), 256, ATT_BYTES>>>(
        pqkv, elev, alpha, pattn);
    // 4. x1 = x + attn @ proj_w + proj_b  (fp32 out)
    tgemm<512, 512, true, false, true, false><<<dim3(4, 64), 128, GSMEM_B>>>(
        pattn, pwt + WT_PROJ, projb, x, px1);
    // 5. LN2 -> fp16
    ln_kernel<<<ROWS, 128>>>(px1, ln2g, ln2b, ph);
    // 6. act = gelu(h2 @ fc1_w + fc1_b) -> fp16
    tgemm<2048, 512, true, true, false, true><<<dim3(16, 64), 128, GSMEM_B>>>(
        ph, pwt + WT_FC1, fc1b, nullptr, pact);
    // 7. out = x1 + act @ fc2_w + fc2_b  (fp32 out)
    tgemm<512, 2048, true, false, true, false><<<dim3(4, 64), 128, GSMEM_B>>>(
        pact, pwt + WT_FC2, fc2b, px1, out);
}

// round 16
// speedup vs baseline: 2.0064x; 1.0776x over previous
#include <cuda_runtime.h>
#include <cuda_fp16.h>
#include <math.h>
#include <stdint.h>

#define Bsz   4
#define Nseq  2048
#define Dm    512
#define Hh    8
#define HDim  64
#define MLPH  2048
#define ROWS  (Bsz * Nseq)
#define SCALE 0.125f
#define LOG2E 1.4426950408889634f
#define SCALE2 (SCALE * LOG2E)

// ---------------- scratch ----------------
__device__ __half g_h[ROWS * Dm];
__device__ __half g_qkv[ROWS * 3 * Dm];
__device__ __half g_attn[ROWS * Dm];
__device__ float  g_x1[ROWS * Dm];
__device__ __half g_act[ROWS * MLPH];
__device__ __half g_wt[3145728];
#define WT_QKV  0
#define WT_PROJ 786432
#define WT_FC1  1048576
#define WT_FC2  2097152

// ---------------- helpers ----------------
__device__ __forceinline__ uint32_t smem_u32(const void* p) {
    return (uint32_t)__cvta_generic_to_shared(p);
}
__device__ __forceinline__ float ex2(float x) {
    float r; asm("ex2.approx.f32 %0, %1;" : "=f"(r) : "f"(x)); return r;
}
__device__ __forceinline__ __half2 hex2_(__half2 x) {
    uint32_t xi = *(uint32_t*)&x, ri;
    asm("ex2.approx.f16x2 %0, %1;" : "=r"(ri) : "r"(xi));
    return *(__half2*)&ri;
}
__device__ __forceinline__ __half2 shfl_h2(__half2 v, int m) {
    uint32_t u = *(uint32_t*)&v;
    u = __shfl_xor_sync(0xffffffffu, u, m);
    return *(__half2*)&u;
}
__device__ __forceinline__ void ldsm4(uint32_t r[4], uint32_t a) {
    asm volatile("ldmatrix.sync.aligned.m8n8.x4.shared.b16 {%0,%1,%2,%3}, [%4];"
        : "=r"(r[0]), "=r"(r[1]), "=r"(r[2]), "=r"(r[3]) : "r"(a));
}
__device__ __forceinline__ void ldsm4t(uint32_t r[4], uint32_t a) {
    asm volatile("ldmatrix.sync.aligned.m8n8.x4.trans.shared.b16 {%0,%1,%2,%3}, [%4];"
        : "=r"(r[0]), "=r"(r[1]), "=r"(r[2]), "=r"(r[3]) : "r"(a));
}
__device__ __forceinline__ void mma16(float d[4], const uint32_t a[4],
                                      uint32_t b0, uint32_t b1) {
    asm volatile(
        "mma.sync.aligned.m16n8k16.row.col.f32.f16.f16.f32 "
        "{%0,%1,%2,%3}, {%4,%5,%6,%7}, {%8,%9}, {%0,%1,%2,%3};"
        : "+f"(d[0]), "+f"(d[1]), "+f"(d[2]), "+f"(d[3])
        : "r"(a[0]), "r"(a[1]), "r"(a[2]), "r"(a[3]), "r"(b0), "r"(b1));
}
__device__ __forceinline__ void cpa16(uint32_t dst, const void* src) {
    asm volatile("cp.async.cg.shared.global [%0], [%1], 16;\n"
        :: "r"(dst), "l"(src));
}
#define CP_COMMIT() asm volatile("cp.async.commit_group;\n" ::: "memory")
#define CP_WAIT1()  asm volatile("cp.async.wait_group 1;\n" ::: "memory")
#define CP_WAIT0()  asm volatile("cp.async.wait_group 0;\n" ::: "memory")

// ---------------- merged weight transpose -> fp16 [n][k] ----------------
__global__ __launch_bounds__(256) void transpose_all(
    const float* __restrict__ qkvw, const float* __restrict__ projw,
    const float* __restrict__ fc1w, const float* __restrict__ fc2w,
    __half* __restrict__ wt)
{
    __shared__ float t[32][33];
    int bid = blockIdx.x;
    const float* in; __half* out; int K, N, rel, nx;
    if (bid < 768)       { in = qkvw;  out = wt + WT_QKV;  K = 512;  N = 1536; rel = bid;        nx = 48; }
    else if (bid < 1024) { in = projw; out = wt + WT_PROJ; K = 512;  N = 512;  rel = bid - 768;  nx = 16; }
    else if (bid < 2048) { in = fc1w;  out = wt + WT_FC1;  K = 512;  N = 2048; rel = bid - 1024; nx = 64; }
    else                 { in = fc2w;  out = wt + WT_FC2;  K = 2048; N = 512;  rel = bid - 2048; nx = 16; }
    int n0 = (rel % nx) * 32, k0 = (rel / nx) * 32;
    int tx = threadIdx.x, ty = threadIdx.y;
    #pragma unroll
    for (int j = 0; j < 32; j += 8)
        t[ty + j][tx] = in[(size_t)(k0 + ty + j) * N + n0 + tx];
    __syncthreads();
    #pragma unroll
    for (int j = 0; j < 32; j += 8)
        out[(size_t)(n0 + ty + j) * K + k0 + tx] = __float2half_rn(t[tx][ty + j]);
}

// ---------------- LayerNorm (fp32 in -> fp16 out) ----------------
__global__ __launch_bounds__(128) void ln_kernel(
    const float* __restrict__ in, const float* __restrict__ gamma,
    const float* __restrict__ beta, __half* __restrict__ out)
{
    int row = blockIdx.x;
    int tid = threadIdx.x;
    const float4* p = (const float4*)(in + (size_t)row * Dm);
    float4 v = p[tid];
    float s  = v.x + v.y + v.z + v.w;
    float ss = v.x * v.x + v.y * v.y + v.z * v.z + v.w * v.w;
    #pragma unroll
    for (int o = 16; o; o >>= 1) {
        s  += __shfl_xor_sync(0xffffffffu, s,  o);
        ss += __shfl_xor_sync(0xffffffffu, ss, o);
    }
    __shared__ float sm[8];
    int w = tid >> 5, lane = tid & 31;
    if (lane == 0) { sm[w] = s; sm[4 + w] = ss; }
    __syncthreads();
    float tot  = sm[0] + sm[1] + sm[2] + sm[3];
    float tot2 = sm[4] + sm[5] + sm[6] + sm[7];
    float mean = tot * (1.0f / Dm);
    float var  = tot2 * (1.0f / Dm) - mean * mean;
    float inv  = rsqrtf(var + 1e-5f);
    float4 g4 = ((const float4*)gamma)[tid];
    float4 b4 = ((const float4*)beta)[tid];
    __half2* op = (__half2*)(out + (size_t)row * Dm);
    op[tid * 2]     = __floats2half2_rn((v.x - mean) * inv * g4.x + b4.x,
                                        (v.y - mean) * inv * g4.y + b4.y);
    op[tid * 2 + 1] = __floats2half2_rn((v.z - mean) * inv * g4.z + b4.z,
                                        (v.w - mean) * inv * g4.w + b4.w);
}

// ---------------- FP16 GEMM ----------------
#define GSTG_B  16384
#define GBOFF   49152
#define GSMEM_B 98304

__device__ __forceinline__ float gelu_exact(float x) {
    return 0.5f * x * (1.0f + erff(x * 0.70710678118654752f));
}

template<int N, int K, bool BIAS, bool GELU, bool RES, bool HOUT, bool SCALEQ>
__global__ __launch_bounds__(128, 2) void tgemm(
    const __half* __restrict__ A, const __half* __restrict__ WT,
    const float* __restrict__ bias, const float* __restrict__ res,
    void* __restrict__ Cv)
{
    extern __shared__ uint32_t gsm[];
    uint32_t smb = smem_u32(gsm);

    int tid = threadIdx.x, lane = tid & 31, warp = tid >> 5;
    int brow = blockIdx.y * 128, bcol = blockIdx.x * 128;
    int wm = (warp >> 1) * 64, wn = (warp & 1) * 64;
    int la = lane & 7, grp = lane >> 3, g = lane >> 2, t = lane & 3;

    int r0 = tid >> 3, kc = tid & 7;
    const __half* Ag = A  + (size_t)(brow + r0) * K + kc * 8;
    const __half* Bg = WT + (size_t)(bcol + r0) * K + kc * 8;
    uint32_t dA = smb + (uint32_t)(r0 * 128 + ((kc ^ (r0 & 7)) << 4));
    uint32_t dB = dA + GBOFF;

    uint32_t aAddr[4];
    #pragma unroll
    for (int mi = 0; mi < 4; mi++) {
        int r = wm + mi * 16 + la + (grp & 1) * 8;
        int c = grp >> 1;
        aAddr[mi] = smb + (uint32_t)(r * 128 + ((c ^ (r & 7)) << 4));
    }
    uint32_t bAddr[4];
    #pragma unroll
    for (int nt = 0; nt < 4; nt++) {
        int n = wn + nt * 16 + (lane & 7) + ((lane >> 4) & 1) * 8;
        int c = (lane >> 3) & 1;
        bAddr[nt] = smb + GBOFF + (uint32_t)(n * 128 + ((c ^ (n & 7)) << 4));
    }

    float acc[4][8][4];
    #pragma unroll
    for (int mi = 0; mi < 4; mi++)
        #pragma unroll
        for (int ni = 0; ni < 8; ni++)
            #pragma unroll
            for (int c = 0; c < 4; c++) acc[mi][ni][c] = 0.0f;

    constexpr int iters = K / 64;

    #pragma unroll
    for (int p = 0; p < 2; p++) {
        uint32_t oa = dA + p * GSTG_B, ob = dB + p * GSTG_B;
        const __half* a = Ag + p * 64;
        const __half* w = Bg + p * 64;
        #pragma unroll
        for (int i = 0; i < 8; i++) {
            cpa16(oa + i * 2048, a + (size_t)i * 16 * K);
            cpa16(ob + i * 2048, w + (size_t)i * 16 * K);
        }
        CP_COMMIT();
    }

    #pragma unroll 1
    for (int it = 0; it < iters; ++it) {
        CP_WAIT1();
        __syncthreads();
        if (it + 2 < iters) {
            uint32_t so = (uint32_t)(((it + 2) % 3) * GSTG_B);
            const __half* a = Ag + (it + 2) * 64;
            const __half* w = Bg + (it + 2) * 64;
            #pragma unroll
            for (int i = 0; i < 8; i++) {
                cpa16(dA + so + i * 2048, a + (size_t)i * 16 * K);
                cpa16(dB + so + i * 2048, w + (size_t)i * 16 * K);
            }
        }
        CP_COMMIT();

        uint32_t so = (uint32_t)((it % 3) * GSTG_B);

        uint32_t af[2][4][4], bf[2][4][4];
        #pragma unroll
        for (int mi = 0; mi < 4; mi++) ldsm4(af[0][mi], aAddr[mi] + so);
        #pragma unroll
        for (int nt = 0; nt < 4; nt++) ldsm4(bf[0][nt], bAddr[nt] + so);

        #pragma unroll
        for (int ks = 0; ks < 4; ks++) {
            int cur = ks & 1, nxt = cur ^ 1;
            if (ks < 3) {
                uint32_t kx = (uint32_t)((ks + 1) << 5);
                #pragma unroll
                for (int mi = 0; mi < 4; mi++)
                    ldsm4(af[nxt][mi], (aAddr[mi] + so) ^ kx);
                #pragma unroll
                for (int nt = 0; nt < 4; nt++)
                    ldsm4(bf[nxt][nt], (bAddr[nt] + so) ^ kx);
            }
            #pragma unroll
            for (int nt = 0; nt < 4; nt++) {
                #pragma unroll
                for (int mi = 0; mi < 4; mi++) {
                    mma16(acc[mi][nt * 2],     af[cur][mi], bf[cur][nt][0], bf[cur][nt][1]);
                    mma16(acc[mi][nt * 2 + 1], af[cur][mi], bf[cur][nt][2], bf[cur][nt][3]);
                }
            }
        }
    }

    float qs = (SCALEQ && bcol < 512) ? SCALE2 : 1.0f;

    #pragma unroll
    for (int mi = 0; mi < 4; mi++) {
        int r0e = brow + wm + mi * 16 + g;
        #pragma unroll
        for (int ni = 0; ni < 8; ni++) {
            int col = bcol + wn + ni * 8 + t * 2;
            float2 v0 = {acc[mi][ni][0], acc[mi][ni][1]};
            float2 v1 = {acc[mi][ni][2], acc[mi][ni][3]};
            if (BIAS) {
                float2 bb = *(const float2*)&bias[col];
                v0.x += bb.x; v0.y += bb.y; v1.x += bb.x; v1.y += bb.y;
            }
            if (GELU) {
                v0.x = gelu_exact(v0.x); v0.y = gelu_exact(v0.y);
                v1.x = gelu_exact(v1.x); v1.y = gelu_exact(v1.y);
            }
            if (RES) {
                float2 q0 = *(const float2*)&res[(size_t)r0e * N + col];
                float2 q1 = *(const float2*)&res[(size_t)(r0e + 8) * N + col];
                v0.x += q0.x; v0.y += q0.y; v1.x += q1.x; v1.y += q1.y;
            }
            if (SCALEQ) {
                v0.x *= qs; v0.y *= qs; v1.x *= qs; v1.y *= qs;
            }
            if (HOUT) {
                __half* C = (__half*)Cv;
                *(__half2*)&C[(size_t)r0e * N + col]       = __floats2half2_rn(v0.x, v0.y);
                *(__half2*)&C[(size_t)(r0e + 8) * N + col] = __floats2half2_rn(v1.x, v1.y);
            } else {
                float* C = (float*)Cv;
                *(float2*)&C[(size_t)r0e * N + col] = v0;
                *(float2*)&C[(size_t)(r0e + 8) * N + col] = v1;
            }
        }
    }
}

// ---------------- FP16 flash attention, half2 softmax, mma row-sums ------
#define KPWH   72
#define AOFF_QP 0
#define AOFF_K  9216
#define AOFF_V  18432
#define AOFF_EK 27648
#define ATT_BYTES 55808
#define KVSTGH  4608
#define ONESH2  0x3C003C00u

__global__ __launch_bounds__(256, 2) void attn_tc(
    const __half* __restrict__ qkv, const float* __restrict__ elev,
    const float* __restrict__ alpha_p, __half* __restrict__ out)
{
    extern __shared__ __half dsm[];
    uint32_t smb = smem_u32(dsm);
    __half* sEKh = dsm + AOFF_EK;

    int bh = blockIdx.y;
    int b = bh >> 3, h = bh & 7;
    int q0 = blockIdx.x * 128;
    int tid = threadIdx.x, lane = tid & 31, warp = tid >> 5;
    int la = lane & 7, grp = lane >> 3, g = lane >> 2, t = lane & 3;
    const float LO = -10.0f * LOG2E;
    float negc2 = -alpha_p[0] * (1e-3f * LOG2E);
    const __half2 zero2 = __float2half2_rn(0.0f);
    const __half2 lo2   = __float2half2_rn(LO);
    const float* eb = elev + b * Nseq;
    const __half* qbase = qkv + ((size_t)(b * Nseq + q0)) * (3 * Dm) + h * HDim;
    const __half* kvb   = qkv + ((size_t)(b * Nseq)) * (3 * Dm) + Dm + h * HDim;

    #pragma unroll
    for (int i = 0; i < 4; i++) {
        int idx = tid + i * 256;
        int r = idx >> 3, c8 = (idx & 7) * 8;
        cpa16(smb + (uint32_t)(AOFF_QP + r * KPWH + c8) * 2u,
              qbase + (size_t)r * (3 * Dm) + c8);
    }
    #pragma unroll
    for (int i = 0; i < 2; i++) {
        int idx = tid + i * 256;
        int r = idx >> 3, c8 = (idx & 7) * 8;
        const __half* src = kvb + (size_t)r * (3 * Dm) + c8;
        cpa16(smb + (uint32_t)(AOFF_K + r * KPWH + c8) * 2u, src);
        cpa16(smb + (uint32_t)(AOFF_V + r * KPWH + c8) * 2u, src + Dm);
    }
    if (tid < 64) sEKh[tid] = __float2half_rn(eb[tid] * negc2);
    CP_COMMIT();
    CP_WAIT0();
    __syncthreads();

    int qr0 = warp * 16;
    uint32_t aAddr = smb +
        (uint32_t)(AOFF_QP + (qr0 + la + (grp & 1) * 8) * KPWH + (grp >> 1) * 8) * 2u;
    uint32_t qf[4][4];
    #pragma unroll
    for (int kc = 0; kc < 4; kc++) ldsm4(qf[kc], aAddr + kc * 32);

    __half2 eq0h2 = __float2half2_rn(eb[q0 + qr0 + g] * negc2);
    __half2 eq1h2 = __float2half2_rn(eb[q0 + qr0 + g + 8] * negc2);

    uint32_t bAddrK[4];
    #pragma unroll
    for (int nt = 0; nt < 4; nt++) {
        int r = nt * 16 + la + (grp >> 1) * 8;
        bAddrK[nt] = smb + (uint32_t)(AOFF_K + r * KPWH + (grp & 1) * 8) * 2u;
    }
    uint32_t vBase[4];
    #pragma unroll
    for (int nt = 0; nt < 4; nt++) {
        vBase[nt] = smb + (uint32_t)(AOFF_V + ((grp & 1) * 8 + la) * KPWH
                                     + nt * 16 + (grp >> 1) * 8) * 2u;
    }

    float O[8][4];
    #pragma unroll
    for (int e = 0; e < 8; e++)
        O[e][0] = O[e][1] = O[e][2] = O[e][3] = 0.0f;
    float lacc[4] = {0.0f, 0.0f, 0.0f, 0.0f};
    float mi0 = -1e30f, mi1 = -1e30f;

    #pragma unroll 1
    for (int tt = 0; tt < Nseq / 64; tt++) {
        if (tt) { CP_WAIT0(); __syncthreads(); }
        if (tt + 1 < Nseq / 64) {
            int bufn = (tt + 1) & 1;
            int k0n = (tt + 1) * 64;
            const __half* kb = kvb + (size_t)k0n * (3 * Dm);
            #pragma unroll
            for (int i = 0; i < 2; i++) {
                int idx = tid + i * 256;
                int r = idx >> 3, c8 = (idx & 7) * 8;
                const __half* src = kb + (size_t)r * (3 * Dm) + c8;
                cpa16(smb + (uint32_t)(AOFF_K + bufn * KVSTGH + r * KPWH + c8) * 2u, src);
                cpa16(smb + (uint32_t)(AOFF_V + bufn * KVSTGH + r * KPWH + c8) * 2u, src + Dm);
            }
            if (tid < 64) sEKh[bufn * 64 + tid] = __float2half_rn(eb[k0n + tid] * negc2);
        }
        CP_COMMIT();

        int buf = tt & 1;
        uint32_t bOff = (uint32_t)(buf * KVSTGH) * 2u;

        // S = Q' K^T (Q pre-scaled by SCALE2)
        float S[8][4];
        #pragma unroll
        for (int nt = 0; nt < 8; nt++)
            S[nt][0] = S[nt][1] = S[nt][2] = S[nt][3] = 0.0f;
        #pragma unroll
        for (int kc = 0; kc < 4; kc++) {
            #pragma unroll
            for (int nt4 = 0; nt4 < 4; nt4++) {
                uint32_t bf[4];
                ldsm4(bf, bAddrK[nt4] + bOff + kc * 32);
                mma16(S[nt4 * 2],     qf[kc], bf[0], bf[1]);
                mma16(S[nt4 * 2 + 1], qf[kc], bf[2], bf[3]);
            }
        }

        // half2 softmax
        __half2 Sh0[8], Sh1[8];
        __half2 rm0 = __float2half2_rn(-60000.0f), rm1 = rm0;
        #pragma unroll
        for (int nt = 0; nt < 8; nt++) {
            __half2 s0 = __floats2half2_rn(S[nt][0], S[nt][1]);
            __half2 s1 = __floats2half2_rn(S[nt][2], S[nt][3]);
            __half2 ek2 = *(const __half2*)&sEKh[buf * 64 + nt * 8 + t * 2];
            s0 = __hadd2(s0, __hmax2(__hmin2(__hsub2(ek2, eq0h2), zero2), lo2));
            s1 = __hadd2(s1, __hmax2(__hmin2(__hsub2(ek2, eq1h2), zero2), lo2));
            Sh0[nt] = s0; Sh1[nt] = s1;
            rm0 = __hmax2(rm0, s0);
            rm1 = __hmax2(rm1, s1);
        }
        rm0 = __hmax2(rm0, shfl_h2(rm0, 1));
        rm0 = __hmax2(rm0, shfl_h2(rm0, 2));
        rm1 = __hmax2(rm1, shfl_h2(rm1, 1));
        rm1 = __hmax2(rm1, shfl_h2(rm1, 2));
        float m0 = fmaxf(mi0, fmaxf(__low2float(rm0), __high2float(rm0)));
        float m1 = fmaxf(mi1, fmaxf(__low2float(rm1), __high2float(rm1)));
        float c0 = ex2(mi0 - m0), c1 = ex2(mi1 - m1);
        mi0 = m0; mi1 = m1;
        __half2 mn0h2 = __float2half2_rn(m0);
        __half2 mn1h2 = __float2half2_rn(m1);

        // p = exp2(S - m), stored directly as fp16 P
        #pragma unroll
        for (int nt = 0; nt < 8; nt++) {
            __half2 p0 = hex2_(__hsub2(Sh0[nt], mn0h2));
            __half2 p1 = hex2_(__hsub2(Sh1[nt], mn1h2));
            *(__half2*)&dsm[AOFF_QP + (qr0 + g) * KPWH + nt * 8 + t * 2] = p0;
            *(__half2*)&dsm[AOFF_QP + (qr0 + 8 + g) * KPWH + nt * 8 + t * 2] = p1;
        }
        // rescale O and l
        lacc[0] *= c0; lacc[2] *= c1;
        #pragma unroll
        for (int e = 0; e < 8; e++) {
            O[e][0] *= c0; O[e][1] *= c0; O[e][2] *= c1; O[e][3] *= c1;
        }
        __syncwarp();

        // O += P @ V ; l += P @ ones
        #pragma unroll
        for (int kc = 0; kc < 4; kc++) {
            uint32_t pf[4];
            ldsm4(pf, aAddr + kc * 32);
            mma16(lacc, pf, ONESH2, ONESH2);
            uint32_t kRow = bOff + (uint32_t)(kc * 16 * KPWH) * 2u;
            #pragma unroll
            for (int nt4 = 0; nt4 < 4; nt4++) {
                uint32_t bf[4];
                ldsm4t(bf, vBase[nt4] + kRow);
                mma16(O[nt4 * 2],     pf, bf[0], bf[1]);
                mma16(O[nt4 * 2 + 1], pf, bf[2], bf[3]);
            }
        }
    }

    float inv0 = 1.0f / lacc[0], inv1 = 1.0f / lacc[2];
    int row0 = b * Nseq + q0 + qr0 + g;
    #pragma unroll
    for (int e = 0; e < 8; e++) {
        int col = h * HDim + e * 8 + t * 2;
        *(__half2*)&out[(size_t)row0 * Dm + col] =
            __floats2half2_rn(O[e][0] * inv0, O[e][1] * inv0);
        *(__half2*)&out[(size_t)(row0 + 8) * Dm + col] =
            __floats2half2_rn(O[e][2] * inv1, O[e][3] * inv1);
    }
}

// ---------------- launch ----------------
extern "C" void kernel_launch(void* const* d_in, const int* in_sizes, int n_in,
                              void* d_out, int out_size)
{
    const float* x     = (const float*)d_in[0];
    const float* elev  = (const float*)d_in[1];
    const float* ln1g  = (const float*)d_in[2];
    const float* ln1b  = (const float*)d_in[3];
    const float* qkvw  = (const float*)d_in[4];
    const float* alpha = (const float*)d_in[5];
    const float* projw = (const float*)d_in[6];
    const float* projb = (const float*)d_in[7];
    const float* ln2g  = (const float*)d_in[8];
    const float* ln2b  = (const float*)d_in[9];
    const float* fc1w  = (const float*)d_in[10];
    const float* fc1b  = (const float*)d_in[11];
    const float* fc2w  = (const float*)d_in[12];
    const float* fc2b  = (const float*)d_in[13];
    float* out = (float*)d_out;

    __half *ph, *pqkv, *pattn, *pact, *pwt;
    float *px1;
    cudaGetSymbolAddress((void**)&ph,    g_h);
    cudaGetSymbolAddress((void**)&pqkv,  g_qkv);
    cudaGetSymbolAddress((void**)&pattn, g_attn);
    cudaGetSymbolAddress((void**)&px1,   g_x1);
    cudaGetSymbolAddress((void**)&pact,  g_act);
    cudaGetSymbolAddress((void**)&pwt,   g_wt);

    cudaFuncSetAttribute(attn_tc,
        cudaFuncAttributeMaxDynamicSharedMemorySize, ATT_BYTES);
    cudaFuncSetAttribute(tgemm<1536, 512, false, false, false, true, true>,
        cudaFuncAttributeMaxDynamicSharedMemorySize, GSMEM_B);
    cudaFuncSetAttribute(tgemm<512, 512, true, false, true, false, false>,
        cudaFuncAttributeMaxDynamicSharedMemorySize, GSMEM_B);
    cudaFuncSetAttribute(tgemm<2048, 512, true, true, false, true, false>,
        cudaFuncAttributeMaxDynamicSharedMemorySize, GSMEM_B);
    cudaFuncSetAttribute(tgemm<512, 2048, true, false, true, false, false>,
        cudaFuncAttributeMaxDynamicSharedMemorySize, GSMEM_B);

    // 0. all weight transposes (fp32 -> fp16 [n][k]) in one launch
    transpose_all<<<3072, dim3(32, 8)>>>(qkvw, projw, fc1w, fc2w, pwt);

    // 1. LN1 -> fp16
    ln_kernel<<<ROWS, 128>>>(x, ln1g, ln1b, ph);
    // 2. qkv = h @ qkv_w -> fp16 (Q columns pre-scaled by SCALE2)
    tgemm<1536, 512, false, false, false, true, true><<<dim3(12, 64), 128, GSMEM_B>>>(
        ph, pwt + WT_QKV, nullptr, nullptr, pqkv);
    // 3. attention -> fp16
    attn_tc<<<dim3(Nseq / 128, Bsz * Hh), 256, ATT_BYTES>>>(
        pqkv, elev, alpha, pattn);
    // 4. x1 = x + attn @ proj_w + proj_b  (fp32 out)
    tgemm<512, 512, true, false, true, false, false><<<dim3(4, 64), 128, GSMEM_B>>>(
        pattn, pwt + WT_PROJ, projb, x, px1);
    // 5. LN2 -> fp16
    ln_kernel<<<ROWS, 128>>>(px1, ln2g, ln2b, ph);
    // 6. act = gelu(h2 @ fc1_w + fc1_b) -> fp16
    tgemm<2048, 512, true, true, false, true, false><<<dim3(16, 64), 128, GSMEM_B>>>(
        ph, pwt + WT_FC1, fc1b, nullptr, pact);
    // 7. out = x1 + act @ fc2_w + fc2_b  (fp32 out)
    tgemm<512, 2048, true, false, true, false, false><<<dim3(4, 64), 128, GSMEM_B>>>(
        pact, pwt + WT_FC2, fc2b, px1, out);
}

// round 17
// speedup vs baseline: 2.0848x; 1.0391x over previous
#include <cuda_runtime.h>
#include <cuda_fp16.h>
#include <math.h>
#include <stdint.h>

#define Bsz   4
#define Nseq  2048
#define Dm    512
#define Hh    8
#define HDim  64
#define MLPH  2048
#define ROWS  (Bsz * Nseq)
#define SCALE 0.125f
#define LOG2E 1.4426950408889634f
#define SCALE2 (SCALE * LOG2E)

// ---------------- scratch ----------------
__device__ __half g_h[ROWS * Dm];
__device__ __half g_qkv[ROWS * 3 * Dm];
__device__ __half g_attn[ROWS * Dm];
__device__ float  g_x1[ROWS * Dm];
__device__ __half g_act[ROWS * MLPH];
__device__ __half g_wt[3145728];
#define WT_QKV  0
#define WT_PROJ 786432
#define WT_FC1  1048576
#define WT_FC2  2097152

// ---------------- helpers ----------------
__device__ __forceinline__ uint32_t smem_u32(const void* p) {
    return (uint32_t)__cvta_generic_to_shared(p);
}
__device__ __forceinline__ float ex2(float x) {
    float r; asm("ex2.approx.f32 %0, %1;" : "=f"(r) : "f"(x)); return r;
}
__device__ __forceinline__ __half2 hex2_(__half2 x) {
    uint32_t xi = *(uint32_t*)&x, ri;
    asm("ex2.approx.f16x2 %0, %1;" : "=r"(ri) : "r"(xi));
    return *(__half2*)&ri;
}
__device__ __forceinline__ __half2 shfl_h2(__half2 v, int m) {
    uint32_t u = *(uint32_t*)&v;
    u = __shfl_xor_sync(0xffffffffu, u, m);
    return *(__half2*)&u;
}
__device__ __forceinline__ void ldsm4(uint32_t r[4], uint32_t a) {
    asm volatile("ldmatrix.sync.aligned.m8n8.x4.shared.b16 {%0,%1,%2,%3}, [%4];"
        : "=r"(r[0]), "=r"(r[1]), "=r"(r[2]), "=r"(r[3]) : "r"(a));
}
__device__ __forceinline__ void ldsm4t(uint32_t r[4], uint32_t a) {
    asm volatile("ldmatrix.sync.aligned.m8n8.x4.trans.shared.b16 {%0,%1,%2,%3}, [%4];"
        : "=r"(r[0]), "=r"(r[1]), "=r"(r[2]), "=r"(r[3]) : "r"(a));
}
__device__ __forceinline__ void mma16(float d[4], const uint32_t a[4],
                                      uint32_t b0, uint32_t b1) {
    asm volatile(
        "mma.sync.aligned.m16n8k16.row.col.f32.f16.f16.f32 "
        "{%0,%1,%2,%3}, {%4,%5,%6,%7}, {%8,%9}, {%0,%1,%2,%3};"
        : "+f"(d[0]), "+f"(d[1]), "+f"(d[2]), "+f"(d[3])
        : "r"(a[0]), "r"(a[1]), "r"(a[2]), "r"(a[3]), "r"(b0), "r"(b1));
}
__device__ __forceinline__ void cpa16(uint32_t dst, const void* src) {
    asm volatile("cp.async.cg.shared.global [%0], [%1], 16;\n"
        :: "r"(dst), "l"(src));
}
#define CP_COMMIT() asm volatile("cp.async.commit_group;\n" ::: "memory")
#define CP_WAIT1()  asm volatile("cp.async.wait_group 1;\n" ::: "memory")
#define CP_WAIT0()  asm volatile("cp.async.wait_group 0;\n" ::: "memory")

// ---------------- merged weight transpose -> fp16 [n][k] ----------------
__global__ __launch_bounds__(256) void transpose_all(
    const float* __restrict__ qkvw, const float* __restrict__ projw,
    const float* __restrict__ fc1w, const float* __restrict__ fc2w,
    __half* __restrict__ wt)
{
    __shared__ float t[32][33];
    int bid = blockIdx.x;
    const float* in; __half* out; int K, N, rel, nx;
    if (bid < 768)       { in = qkvw;  out = wt + WT_QKV;  K = 512;  N = 1536; rel = bid;        nx = 48; }
    else if (bid < 1024) { in = projw; out = wt + WT_PROJ; K = 512;  N = 512;  rel = bid - 768;  nx = 16; }
    else if (bid < 2048) { in = fc1w;  out = wt + WT_FC1;  K = 512;  N = 2048; rel = bid - 1024; nx = 64; }
    else                 { in = fc2w;  out = wt + WT_FC2;  K = 2048; N = 512;  rel = bid - 2048; nx = 16; }
    int n0 = (rel % nx) * 32, k0 = (rel / nx) * 32;
    int tx = threadIdx.x, ty = threadIdx.y;
    #pragma unroll
    for (int j = 0; j < 32; j += 8)
        t[ty + j][tx] = in[(size_t)(k0 + ty + j) * N + n0 + tx];
    __syncthreads();
    #pragma unroll
    for (int j = 0; j < 32; j += 8)
        out[(size_t)(n0 + ty + j) * K + k0 + tx] = __float2half_rn(t[tx][ty + j]);
}

// ---------------- LayerNorm (fp32 in -> fp16 out) ----------------
__global__ __launch_bounds__(128) void ln_kernel(
    const float* __restrict__ in, const float* __restrict__ gamma,
    const float* __restrict__ beta, __half* __restrict__ out)
{
    int row = blockIdx.x;
    int tid = threadIdx.x;
    const float4* p = (const float4*)(in + (size_t)row * Dm);
    float4 v = p[tid];
    float s  = v.x + v.y + v.z + v.w;
    float ss = v.x * v.x + v.y * v.y + v.z * v.z + v.w * v.w;
    #pragma unroll
    for (int o = 16; o; o >>= 1) {
        s  += __shfl_xor_sync(0xffffffffu, s,  o);
        ss += __shfl_xor_sync(0xffffffffu, ss, o);
    }
    __shared__ float sm[8];
    int w = tid >> 5, lane = tid & 31;
    if (lane == 0) { sm[w] = s; sm[4 + w] = ss; }
    __syncthreads();
    float tot  = sm[0] + sm[1] + sm[2] + sm[3];
    float tot2 = sm[4] + sm[5] + sm[6] + sm[7];
    float mean = tot * (1.0f / Dm);
    float var  = tot2 * (1.0f / Dm) - mean * mean;
    float inv  = rsqrtf(var + 1e-5f);
    float4 g4 = ((const float4*)gamma)[tid];
    float4 b4 = ((const float4*)beta)[tid];
    __half2* op = (__half2*)(out + (size_t)row * Dm);
    op[tid * 2]     = __floats2half2_rn((v.x - mean) * inv * g4.x + b4.x,
                                        (v.y - mean) * inv * g4.y + b4.y);
    op[tid * 2 + 1] = __floats2half2_rn((v.z - mean) * inv * g4.z + b4.z,
                                        (v.w - mean) * inv * g4.w + b4.w);
}

// ---------------- FP16 GEMM ----------------
#define GSTG_B  16384
#define GBOFF   49152
#define GSMEM_B 98304

__device__ __forceinline__ float gelu_exact(float x) {
    return 0.5f * x * (1.0f + erff(x * 0.70710678118654752f));
}

template<int N, int K, bool BIAS, bool GELU, bool RES, bool HOUT, bool SCALEQ>
__global__ __launch_bounds__(128, 2) void tgemm(
    const __half* __restrict__ A, const __half* __restrict__ WT,
    const float* __restrict__ bias, const float* __restrict__ res,
    void* __restrict__ Cv)
{
    extern __shared__ uint32_t gsm[];
    uint32_t smb = smem_u32(gsm);

    int tid = threadIdx.x, lane = tid & 31, warp = tid >> 5;
    int brow = blockIdx.y * 128, bcol = blockIdx.x * 128;
    int wm = (warp >> 1) * 64, wn = (warp & 1) * 64;
    int la = lane & 7, grp = lane >> 3, g = lane >> 2, t = lane & 3;

    int r0 = tid >> 3, kc = tid & 7;
    const __half* Ag = A  + (size_t)(brow + r0) * K + kc * 8;
    const __half* Bg = WT + (size_t)(bcol + r0) * K + kc * 8;
    uint32_t dA = smb + (uint32_t)(r0 * 128 + ((kc ^ (r0 & 7)) << 4));
    uint32_t dB = dA + GBOFF;

    uint32_t aAddr[4];
    #pragma unroll
    for (int mi = 0; mi < 4; mi++) {
        int r = wm + mi * 16 + la + (grp & 1) * 8;
        int c = grp >> 1;
        aAddr[mi] = smb + (uint32_t)(r * 128 + ((c ^ (r & 7)) << 4));
    }
    uint32_t bAddr[4];
    #pragma unroll
    for (int nt = 0; nt < 4; nt++) {
        int n = wn + nt * 16 + (lane & 7) + ((lane >> 4) & 1) * 8;
        int c = (lane >> 3) & 1;
        bAddr[nt] = smb + GBOFF + (uint32_t)(n * 128 + ((c ^ (n & 7)) << 4));
    }

    float acc[4][8][4];
    #pragma unroll
    for (int mi = 0; mi < 4; mi++)
        #pragma unroll
        for (int ni = 0; ni < 8; ni++)
            #pragma unroll
            for (int c = 0; c < 4; c++) acc[mi][ni][c] = 0.0f;

    constexpr int iters = K / 64;

    #pragma unroll
    for (int p = 0; p < 2; p++) {
        uint32_t oa = dA + p * GSTG_B, ob = dB + p * GSTG_B;
        const __half* a = Ag + p * 64;
        const __half* w = Bg + p * 64;
        #pragma unroll
        for (int i = 0; i < 8; i++) {
            cpa16(oa + i * 2048, a + (size_t)i * 16 * K);
            cpa16(ob + i * 2048, w + (size_t)i * 16 * K);
        }
        CP_COMMIT();
    }

    #pragma unroll 1
    for (int it = 0; it < iters; ++it) {
        CP_WAIT1();
        __syncthreads();
        if (it + 2 < iters) {
            uint32_t so = (uint32_t)(((it + 2) % 3) * GSTG_B);
            const __half* a = Ag + (it + 2) * 64;
            const __half* w = Bg + (it + 2) * 64;
            #pragma unroll
            for (int i = 0; i < 8; i++) {
                cpa16(dA + so + i * 2048, a + (size_t)i * 16 * K);
                cpa16(dB + so + i * 2048, w + (size_t)i * 16 * K);
            }
        }
        CP_COMMIT();

        uint32_t so = (uint32_t)((it % 3) * GSTG_B);

        uint32_t af[2][4][4], bf[2][4][4];
        #pragma unroll
        for (int mi = 0; mi < 4; mi++) ldsm4(af[0][mi], aAddr[mi] + so);
        #pragma unroll
        for (int nt = 0; nt < 4; nt++) ldsm4(bf[0][nt], bAddr[nt] + so);

        #pragma unroll
        for (int ks = 0; ks < 4; ks++) {
            int cur = ks & 1, nxt = cur ^ 1;
            if (ks < 3) {
                uint32_t kx = (uint32_t)((ks + 1) << 5);
                #pragma unroll
                for (int mi = 0; mi < 4; mi++)
                    ldsm4(af[nxt][mi], (aAddr[mi] + so) ^ kx);
                #pragma unroll
                for (int nt = 0; nt < 4; nt++)
                    ldsm4(bf[nxt][nt], (bAddr[nt] + so) ^ kx);
            }
            #pragma unroll
            for (int nt = 0; nt < 4; nt++) {
                #pragma unroll
                for (int mi = 0; mi < 4; mi++) {
                    mma16(acc[mi][nt * 2],     af[cur][mi], bf[cur][nt][0], bf[cur][nt][1]);
                    mma16(acc[mi][nt * 2 + 1], af[cur][mi], bf[cur][nt][2], bf[cur][nt][3]);
                }
            }
        }
    }

    float qs = (SCALEQ && bcol < 512) ? SCALE2 : 1.0f;

    #pragma unroll
    for (int mi = 0; mi < 4; mi++) {
        int r0e = brow + wm + mi * 16 + g;
        #pragma unroll
        for (int ni = 0; ni < 8; ni++) {
            int col = bcol + wn + ni * 8 + t * 2;
            float2 v0 = {acc[mi][ni][0], acc[mi][ni][1]};
            float2 v1 = {acc[mi][ni][2], acc[mi][ni][3]};
            if (BIAS) {
                float2 bb = *(const float2*)&bias[col];
                v0.x += bb.x; v0.y += bb.y; v1.x += bb.x; v1.y += bb.y;
            }
            if (GELU) {
                v0.x = gelu_exact(v0.x); v0.y = gelu_exact(v0.y);
                v1.x = gelu_exact(v1.x); v1.y = gelu_exact(v1.y);
            }
            if (RES) {
                float2 q0 = *(const float2*)&res[(size_t)r0e * N + col];
                float2 q1 = *(const float2*)&res[(size_t)(r0e + 8) * N + col];
                v0.x += q0.x; v0.y += q0.y; v1.x += q1.x; v1.y += q1.y;
            }
            if (SCALEQ) {
                v0.x *= qs; v0.y *= qs; v1.x *= qs; v1.y *= qs;
            }
            if (HOUT) {
                __half* C = (__half*)Cv;
                *(__half2*)&C[(size_t)r0e * N + col]       = __floats2half2_rn(v0.x, v0.y);
                *(__half2*)&C[(size_t)(r0e + 8) * N + col] = __floats2half2_rn(v1.x, v1.y);
            } else {
                float* C = (float*)Cv;
                *(float2*)&C[(size_t)r0e * N + col] = v0;
                *(float2*)&C[(size_t)(r0e + 8) * N + col] = v1;
            }
        }
    }
}

// ---------------- FP16 flash attention: P stays in registers -------------
#define KPWH   72
#define AOFF_QP 0
#define AOFF_K  9216
#define AOFF_V  18432
#define AOFF_EK 27648
#define ATT_BYTES 55808
#define KVSTGH  4608
#define ONESH2  0x3C003C00u

__global__ __launch_bounds__(256, 2) void attn_tc(
    const __half* __restrict__ qkv, const float* __restrict__ elev,
    const float* __restrict__ alpha_p, __half* __restrict__ out)
{
    extern __shared__ __half dsm[];
    uint32_t smb = smem_u32(dsm);
    __half* sEKh = dsm + AOFF_EK;

    int bh = blockIdx.y;
    int b = bh >> 3, h = bh & 7;
    int q0 = blockIdx.x * 128;
    int tid = threadIdx.x, lane = tid & 31, warp = tid >> 5;
    int la = lane & 7, grp = lane >> 3, g = lane >> 2, t = lane & 3;
    const float LO = -10.0f * LOG2E;
    float negc2 = -alpha_p[0] * (1e-3f * LOG2E);
    const __half2 zero2 = __float2half2_rn(0.0f);
    const __half2 lo2   = __float2half2_rn(LO);
    const float* eb = elev + b * Nseq;
    const __half* qbase = qkv + ((size_t)(b * Nseq + q0)) * (3 * Dm) + h * HDim;
    const __half* kvb   = qkv + ((size_t)(b * Nseq)) * (3 * Dm) + Dm + h * HDim;

    #pragma unroll
    for (int i = 0; i < 4; i++) {
        int idx = tid + i * 256;
        int r = idx >> 3, c8 = (idx & 7) * 8;
        cpa16(smb + (uint32_t)(AOFF_QP + r * KPWH + c8) * 2u,
              qbase + (size_t)r * (3 * Dm) + c8);
    }
    #pragma unroll
    for (int i = 0; i < 2; i++) {
        int idx = tid + i * 256;
        int r = idx >> 3, c8 = (idx & 7) * 8;
        const __half* src = kvb + (size_t)r * (3 * Dm) + c8;
        cpa16(smb + (uint32_t)(AOFF_K + r * KPWH + c8) * 2u, src);
        cpa16(smb + (uint32_t)(AOFF_V + r * KPWH + c8) * 2u, src + Dm);
    }
    if (tid < 64) sEKh[tid] = __float2half_rn(eb[tid] * negc2);
    CP_COMMIT();
    CP_WAIT0();
    __syncthreads();

    int qr0 = warp * 16;
    uint32_t aAddr = smb +
        (uint32_t)(AOFF_QP + (qr0 + la + (grp & 1) * 8) * KPWH + (grp >> 1) * 8) * 2u;
    uint32_t qf[4][4];
    #pragma unroll
    for (int kc = 0; kc < 4; kc++) ldsm4(qf[kc], aAddr + kc * 32);

    __half2 eq0h2 = __float2half2_rn(eb[q0 + qr0 + g] * negc2);
    __half2 eq1h2 = __float2half2_rn(eb[q0 + qr0 + g + 8] * negc2);

    uint32_t bAddrK[4];
    #pragma unroll
    for (int nt = 0; nt < 4; nt++) {
        int r = nt * 16 + la + (grp >> 1) * 8;
        bAddrK[nt] = smb + (uint32_t)(AOFF_K + r * KPWH + (grp & 1) * 8) * 2u;
    }
    uint32_t vBase[4];
    #pragma unroll
    for (int nt = 0; nt < 4; nt++) {
        vBase[nt] = smb + (uint32_t)(AOFF_V + ((grp & 1) * 8 + la) * KPWH
                                     + nt * 16 + (grp >> 1) * 8) * 2u;
    }

    float O[8][4];
    #pragma unroll
    for (int e = 0; e < 8; e++)
        O[e][0] = O[e][1] = O[e][2] = O[e][3] = 0.0f;
    float lacc[4] = {0.0f, 0.0f, 0.0f, 0.0f};
    float mi0 = -1e30f, mi1 = -1e30f;

    #pragma unroll 1
    for (int tt = 0; tt < Nseq / 64; tt++) {
        if (tt) { CP_WAIT0(); __syncthreads(); }
        if (tt + 1 < Nseq / 64) {
            int bufn = (tt + 1) & 1;
            int k0n = (tt + 1) * 64;
            const __half* kb = kvb + (size_t)k0n * (3 * Dm);
            #pragma unroll
            for (int i = 0; i < 2; i++) {
                int idx = tid + i * 256;
                int r = idx >> 3, c8 = (idx & 7) * 8;
                const __half* src = kb + (size_t)r * (3 * Dm) + c8;
                cpa16(smb + (uint32_t)(AOFF_K + bufn * KVSTGH + r * KPWH + c8) * 2u, src);
                cpa16(smb + (uint32_t)(AOFF_V + bufn * KVSTGH + r * KPWH + c8) * 2u, src + Dm);
            }
            if (tid < 64) sEKh[bufn * 64 + tid] = __float2half_rn(eb[k0n + tid] * negc2);
        }
        CP_COMMIT();

        int buf = tt & 1;
        uint32_t bOff = (uint32_t)(buf * KVSTGH) * 2u;

        // S = Q' K^T (Q pre-scaled by SCALE2)
        float S[8][4];
        #pragma unroll
        for (int nt = 0; nt < 8; nt++)
            S[nt][0] = S[nt][1] = S[nt][2] = S[nt][3] = 0.0f;
        #pragma unroll
        for (int kc = 0; kc < 4; kc++) {
            #pragma unroll
            for (int nt4 = 0; nt4 < 4; nt4++) {
                uint32_t bf[4];
                ldsm4(bf, bAddrK[nt4] + bOff + kc * 32);
                mma16(S[nt4 * 2],     qf[kc], bf[0], bf[1]);
                mma16(S[nt4 * 2 + 1], qf[kc], bf[2], bf[3]);
            }
        }

        // half2 softmax
        __half2 Sh0[8], Sh1[8];
        __half2 rm0 = __float2half2_rn(-60000.0f), rm1 = rm0;
        #pragma unroll
        for (int nt = 0; nt < 8; nt++) {
            __half2 s0 = __floats2half2_rn(S[nt][0], S[nt][1]);
            __half2 s1 = __floats2half2_rn(S[nt][2], S[nt][3]);
            __half2 ek2 = *(const __half2*)&sEKh[buf * 64 + nt * 8 + t * 2];
            s0 = __hadd2(s0, __hmax2(__hmin2(__hsub2(ek2, eq0h2), zero2), lo2));
            s1 = __hadd2(s1, __hmax2(__hmin2(__hsub2(ek2, eq1h2), zero2), lo2));
            Sh0[nt] = s0; Sh1[nt] = s1;
            rm0 = __hmax2(rm0, s0);
            rm1 = __hmax2(rm1, s1);
        }
        rm0 = __hmax2(rm0, shfl_h2(rm0, 1));
        rm0 = __hmax2(rm0, shfl_h2(rm0, 2));
        rm1 = __hmax2(rm1, shfl_h2(rm1, 1));
        rm1 = __hmax2(rm1, shfl_h2(rm1, 2));
        float m0 = fmaxf(mi0, fmaxf(__low2float(rm0), __high2float(rm0)));
        float m1 = fmaxf(mi1, fmaxf(__low2float(rm1), __high2float(rm1)));
        float c0 = ex2(mi0 - m0), c1 = ex2(mi1 - m1);
        mi0 = m0; mi1 = m1;
        __half2 mn0h2 = __float2half2_rn(m0);
        __half2 mn1h2 = __float2half2_rn(m1);

        // p = exp2(S - m), kept in registers (C-frag == A-frag layout)
        #pragma unroll
        for (int nt = 0; nt < 8; nt++) {
            Sh0[nt] = hex2_(__hsub2(Sh0[nt], mn0h2));
            Sh1[nt] = hex2_(__hsub2(Sh1[nt], mn1h2));
        }
        // rescale O and l
        lacc[0] *= c0; lacc[2] *= c1;
        #pragma unroll
        for (int e = 0; e < 8; e++) {
            O[e][0] *= c0; O[e][1] *= c0; O[e][2] *= c1; O[e][3] *= c1;
        }

        // O += P @ V ; l += P @ ones  (P fragments straight from registers)
        #pragma unroll
        for (int kc = 0; kc < 4; kc++) {
            uint32_t pf[4];
            pf[0] = *(uint32_t*)&Sh0[2 * kc];
            pf[1] = *(uint32_t*)&Sh1[2 * kc];
            pf[2] = *(uint32_t*)&Sh0[2 * kc + 1];
            pf[3] = *(uint32_t*)&Sh1[2 * kc + 1];
            mma16(lacc, pf, ONESH2, ONESH2);
            uint32_t kRow = bOff + (uint32_t)(kc * 16 * KPWH) * 2u;
            #pragma unroll
            for (int nt4 = 0; nt4 < 4; nt4++) {
                uint32_t bf[4];
                ldsm4t(bf, vBase[nt4] + kRow);
                mma16(O[nt4 * 2],     pf, bf[0], bf[1]);
                mma16(O[nt4 * 2 + 1], pf, bf[2], bf[3]);
            }
        }
    }

    float inv0 = 1.0f / lacc[0], inv1 = 1.0f / lacc[2];
    int row0 = b * Nseq + q0 + qr0 + g;
    #pragma unroll
    for (int e = 0; e < 8; e++) {
        int col = h * HDim + e * 8 + t * 2;
        *(__half2*)&out[(size_t)row0 * Dm + col] =
            __floats2half2_rn(O[e][0] * inv0, O[e][1] * inv0);
        *(__half2*)&out[(size_t)(row0 + 8) * Dm + col] =
            __floats2half2_rn(O[e][2] * inv1, O[e][3] * inv1);
    }
}

// ---------------- launch ----------------
extern "C" void kernel_launch(void* const* d_in, const int* in_sizes, int n_in,
                              void* d_out, int out_size)
{
    const float* x     = (const float*)d_in[0];
    const float* elev  = (const float*)d_in[1];
    const float* ln1g  = (const float*)d_in[2];
    const float* ln1b  = (const float*)d_in[3];
    const float* qkvw  = (const float*)d_in[4];
    const float* alpha = (const float*)d_in[5];
    const float* projw = (const float*)d_in[6];
    const float* projb = (const float*)d_in[7];
    const float* ln2g  = (const float*)d_in[8];
    const float* ln2b  = (const float*)d_in[9];
    const float* fc1w  = (const float*)d_in[10];
    const float* fc1b  = (const float*)d_in[11];
    const float* fc2w  = (const float*)d_in[12];
    const float* fc2b  = (const float*)d_in[13];
    float* out = (float*)d_out;

    __half *ph, *pqkv, *pattn, *pact, *pwt;
    float *px1;
    cudaGetSymbolAddress((void**)&ph,    g_h);
    cudaGetSymbolAddress((void**)&pqkv,  g_qkv);
    cudaGetSymbolAddress((void**)&pattn, g_attn);
    cudaGetSymbolAddress((void**)&px1,   g_x1);
    cudaGetSymbolAddress((void**)&pact,  g_act);
    cudaGetSymbolAddress((void**)&pwt,   g_wt);

    cudaFuncSetAttribute(attn_tc,
        cudaFuncAttributeMaxDynamicSharedMemorySize, ATT_BYTES);
    cudaFuncSetAttribute(tgemm<1536, 512, false, false, false, true, true>,
        cudaFuncAttributeMaxDynamicSharedMemorySize, GSMEM_B);
    cudaFuncSetAttribute(tgemm<512, 512, true, false, true, false, false>,
        cudaFuncAttributeMaxDynamicSharedMemorySize, GSMEM_B);
    cudaFuncSetAttribute(tgemm<2048, 512, true, true, false, true, false>,
        cudaFuncAttributeMaxDynamicSharedMemorySize, GSMEM_B);
    cudaFuncSetAttribute(tgemm<512, 2048, true, false, true, false, false>,
        cudaFuncAttributeMaxDynamicSharedMemorySize, GSMEM_B);

    // 0. all weight transposes (fp32 -> fp16 [n][k]) in one launch
    transpose_all<<<3072, dim3(32, 8)>>>(qkvw, projw, fc1w, fc2w, pwt);

    // 1. LN1 -> fp16
    ln_kernel<<<ROWS, 128>>>(x, ln1g, ln1b, ph);
    // 2. qkv = h @ qkv_w -> fp16 (Q columns pre-scaled by SCALE2)
    tgemm<1536, 512, false, false, false, true, true><<<dim3(12, 64), 128, GSMEM_B>>>(
        ph, pwt + WT_QKV, nullptr, nullptr, pqkv);
    // 3. attention -> fp16
    attn_tc<<<dim3(Nseq / 128, Bsz * Hh), 256, ATT_BYTES>>>(
        pqkv, elev, alpha, pattn);
    // 4. x1 = x + attn @ proj_w + proj_b  (fp32 out)
    tgemm<512, 512, true, false, true, false, false><<<dim3(4, 64), 128, GSMEM_B>>>(
        pattn, pwt + WT_PROJ, projb, x, px1);
    // 5. LN2 -> fp16
    ln_kernel<<<ROWS, 128>>>(px1, ln2g, ln2b, ph);
    // 6. act = gelu(h2 @ fc1_w + fc1_b) -> fp16
    tgemm<2048, 512, true, true, false, true, false><<<dim3(16, 64), 128, GSMEM_B>>>(
        ph, pwt + WT_FC1, fc1b, nullptr, pact);
    // 7. out = x1 + act @ fc2_w + fc2_b  (fp32 out)
    tgemm<512, 2048, true, false, true, false, false><<<dim3(4, 64), 128, GSMEM_B>>>(
        pact, pwt + WT_FC2, fc2b, px1, out);
}